// round 13
// baseline (speedup 1.0000x reference)
#include <cuda_runtime.h>
#include <cuda_fp16.h>
#include <cstdint>

#define B_   8
#define C_   512
#define HW_  4096
#define D_   64
#define BN   256
#define BM   64
#define LOG2E 1.4426950408889634f

// Projected operands, fp16 splits.
// Q,K: [b][n][64] row-major (hi+lo). V: [b][dd][HW] d-major (hi only).
__device__ __half g_Qh[(size_t)B_ * HW_ * D_];
__device__ __half g_Ql[(size_t)B_ * HW_ * D_];
__device__ __half g_Kh[(size_t)B_ * HW_ * D_];
__device__ __half g_Kl[(size_t)B_ * HW_ * D_];
__device__ __half g_Vh[(size_t)B_ * D_ * HW_];

__device__ __forceinline__ float ex2f(float x) {
    float y; asm("ex2.approx.ftz.f32 %0, %1;" : "=f"(y) : "f"(x)); return y;
}
// pack two f32 -> f16x2 (lo_val in low half)
__device__ __forceinline__ uint32_t packhf(float lo_val, float hi_val) {
    uint32_t r;
    asm("cvt.rn.f16x2.f32 %0, %1, %2;" : "=r"(r) : "f"(hi_val), "f"(lo_val));
    return r;
}
// unpack f16x2 -> two f32
__device__ __forceinline__ void uph2(uint32_t h, float& lo, float& hi) {
    asm("{ .reg .b16 l, h; mov.b32 {l, h}, %2; cvt.f32.f16 %0, l; cvt.f32.f16 %1, h; }"
        : "=f"(lo), "=f"(hi) : "r"(h));
}
__device__ __forceinline__ uint32_t smem_u32(const void* p) {
    uint32_t a;
    asm("{ .reg .u64 t; cvta.to.shared.u64 t, %1; cvt.u32.u64 %0, t; }"
        : "=r"(a) : "l"(p));
    return a;
}

#define SWZ128(x) ((x) ^ (((x) >> 3) & 0x70))

__device__ __forceinline__ void ldsm4(uint32_t r[4], uint32_t a) {
    asm volatile("ldmatrix.sync.aligned.m8n8.x4.shared.b16 {%0,%1,%2,%3}, [%4];"
        : "=r"(r[0]), "=r"(r[1]), "=r"(r[2]), "=r"(r[3]) : "r"(a));
}
__device__ __forceinline__ void ldsm4t(uint32_t r[4], uint32_t a) {
    asm volatile("ldmatrix.sync.aligned.m8n8.x4.trans.shared.b16 {%0,%1,%2,%3}, [%4];"
        : "=r"(r[0]), "=r"(r[1]), "=r"(r[2]), "=r"(r[3]) : "r"(a));
}
__device__ __forceinline__ void mma_hf(float d[4], const uint32_t a[4],
                                       uint32_t b0, uint32_t b1) {
    asm volatile("mma.sync.aligned.m16n8k16.row.col.f32.f16.f16.f32 "
        "{%0,%1,%2,%3}, {%4,%5,%6,%7}, {%8,%9}, {%0,%1,%2,%3};"
        : "+f"(d[0]), "+f"(d[1]), "+f"(d[2]), "+f"(d[3])
        : "r"(a[0]), "r"(a[1]), "r"(a[2]), "r"(a[3]), "r"(b0), "r"(b1));
}
__device__ __forceinline__ void cpa16(uint32_t s, const void* g) {
    asm volatile("cp.async.cg.shared.global [%0], [%1], 16;" :: "r"(s), "l"(g));
}
#define CP_COMMIT() asm volatile("cp.async.commit_group;" ::: "memory")
#define CP_WAIT0()  asm volatile("cp.async.wait_group 0;" ::: "memory")
#define BAR_SYNC(id) asm volatile("bar.sync %0, 128;" :: "r"(id) : "memory")

// ---------------------------------------------------------------------------
// HMMA projection (z = 0:Q, 1:K, 2:V). D[d][n] = sum_c w[d][c] x[c][n] (+bias).
// fp16-split MMA: 3-term for Q/K, 2-term for V. CTA = 128n x 64d, K=512.
// 2 CTAs/SM (<=128 regs): cross-CTA overlap hides the staging-load latency,
// replacing the register-prefetch scheme (which forced 1 CTA/SM).
// ---------------------------------------------------------------------------
__global__ __launch_bounds__(256, 2) void proj_kernel(
    const float* __restrict__ xq, const float* __restrict__ xk, const float* __restrict__ xv,
    const float* __restrict__ wq, const float* __restrict__ bq,
    const float* __restrict__ wk, const float* __restrict__ bk,
    const float* __restrict__ wv, const float* __restrict__ bv)
{
    extern __shared__ char psm[];
    const int sel = blockIdx.z;
    const float* x = (sel == 0) ? xq : (sel == 1) ? xk : xv;
    const float* w = (sel == 0) ? wq : (sel == 1) ? wk : wv;
    const float* bias = (sel == 0) ? bq : (sel == 1) ? bk : bv;

    const int b  = blockIdx.y;
    const int n0 = blockIdx.x * 128;
    const int t  = threadIdx.x, lane = t & 31, wid = t >> 5;
    const int wm = wid >> 2, wn = wid & 3;     // warp grid: 2 (d) x 4 (n)
    const uint32_t sb = smem_u32(psm);

    const float* xb = x + (size_t)b * C_ * HW_ + n0;

    float acc[2][4][4] = {};                   // [mt 16d][nt 8n][frag]

    for (int kc = 0; kc < C_; kc += 64) {
        __syncthreads();
        // x tile: 64c x 128n fp32 -> fp16 h/l, SW128 rows of 64n.
        #pragma unroll
        for (int i = 0; i < 8; i++) {
            int idx = t + 256 * i;
            int c = idx >> 5, n = (idx & 31) * 4;
            float4 xv4 = *(const float4*)&xb[(size_t)(kc + c) * HW_ + n];
            uint32_t h0 = packhf(xv4.x, xv4.y), h1 = packhf(xv4.z, xv4.w);
            float f0, f1, f2, f3;
            uph2(h0, f0, f1); uph2(h1, f2, f3);
            uint32_t l0 = packhf(xv4.x - f0, xv4.y - f1);
            uint32_t l1 = packhf(xv4.z - f2, xv4.w - f3);
            int sub = n >> 6, nn = n & 63;
            uint32_t off = (uint32_t)(sub * 8192 + c * 128 + ((nn * 2) ^ ((c & 7) << 4)));
            *(uint2*)(psm + off)         = make_uint2(h0, h1);
            *(uint2*)(psm + 16384 + off) = make_uint2(l0, l1);
        }
        // w tile: 64d x 64c fp32 -> fp16 h/l, SW128 rows.
        #pragma unroll
        for (int i = 0; i < 4; i++) {
            int idx = t + 256 * i;
            int d = idx >> 4, c = (idx & 15) * 4;
            float4 wv4 = *(const float4*)&w[(size_t)d * C_ + kc + c];
            uint32_t h0 = packhf(wv4.x, wv4.y), h1 = packhf(wv4.z, wv4.w);
            float f0, f1, f2, f3;
            uph2(h0, f0, f1); uph2(h1, f2, f3);
            uint32_t l0 = packhf(wv4.x - f0, wv4.y - f1);
            uint32_t l1 = packhf(wv4.z - f2, wv4.w - f3);
            uint32_t off = (uint32_t)(d * 128 + ((c * 2) ^ ((d & 7) << 4)));
            *(uint2*)(psm + 32768 + off) = make_uint2(h0, h1);
            *(uint2*)(psm + 40960 + off) = make_uint2(l0, l1);
        }
        __syncthreads();

        #pragma unroll
        for (int kt = 0; kt < 4; kt++) {
            uint32_t ah[2][4], al[2][4];
            #pragma unroll
            for (int mt = 0; mt < 2; mt++) {
                int row = wm * 32 + mt * 16 + (lane & 15);
                uint32_t off = (uint32_t)(row * 128 +
                    ((kt * 32 + ((lane >> 4) << 4)) ^ ((row & 7) << 4)));
                ldsm4(ah[mt], sb + 32768 + off);
                ldsm4(al[mt], sb + 40960 + off);
            }
            uint32_t bh[8], bl[8];
            #pragma unroll
            for (int hf = 0; hf < 2; hf++) {
                int krow = kt * 16 + (lane & 15);
                int ncol = wn * 32 + hf * 16 + ((lane >> 4) << 3);
                int sub = ncol >> 6, nn = ncol & 63;
                uint32_t off = (uint32_t)(sub * 8192 + krow * 128 +
                    ((nn * 2) ^ ((krow & 7) << 4)));
                ldsm4t(&bh[4 * hf], sb + off);
                ldsm4t(&bl[4 * hf], sb + 16384 + off);
            }
            #pragma unroll
            for (int mt = 0; mt < 2; mt++)
                #pragma unroll
                for (int nt = 0; nt < 4; nt++) {
                    int ib = (nt >> 1) * 4 + (nt & 1) * 2;
                    mma_hf(acc[mt][nt], ah[mt], bh[ib], bh[ib + 1]);
                    mma_hf(acc[mt][nt], ah[mt], bl[ib], bl[ib + 1]);
                    if (sel != 2)
                        mma_hf(acc[mt][nt], al[mt], bh[ib], bh[ib + 1]);
                }
        }
    }

    const int g = lane >> 2, tig = lane & 3;

    if (sel == 2) {
        // V: D[d][n] matches gmem layout -> direct frag stores (hi only).
        #pragma unroll
        for (int mt = 0; mt < 2; mt++) {
            int d0 = wm * 32 + mt * 16 + g, d1 = d0 + 8;
            float b0 = bias[d0], b1 = bias[d1];
            #pragma unroll
            for (int nt = 0; nt < 4; nt++) {
                int n = n0 + wn * 32 + nt * 8 + 2 * tig;
                uint32_t h0 = packhf(acc[mt][nt][0] + b0, acc[mt][nt][1] + b0);
                size_t o0 = ((size_t)b * 64 + d0) * HW_ + n;
                *(uint32_t*)&g_Vh[o0] = h0;
                uint32_t h1 = packhf(acc[mt][nt][2] + b1, acc[mt][nt][3] + b1);
                size_t o1 = ((size_t)b * 64 + d1) * HW_ + n;
                *(uint32_t*)&g_Vh[o1] = h1;
            }
        }
    } else {
        // Q/K: stage D as osm[n][68] fp32, then coalesced [n][64] h/l writes.
        __syncthreads();
        float* osm = (float*)psm;
        const float scale = (sel == 0) ? LOG2E : 1.0f;
        #pragma unroll
        for (int mt = 0; mt < 2; mt++) {
            int d0 = wm * 32 + mt * 16 + g, d1 = d0 + 8;
            float b0 = bias[d0], b1 = bias[d1];
            #pragma unroll
            for (int nt = 0; nt < 4; nt++) {
                int n = wn * 32 + nt * 8 + 2 * tig;
                osm[n * 68 + d0]       = (acc[mt][nt][0] + b0) * scale;
                osm[(n + 1) * 68 + d0] = (acc[mt][nt][1] + b0) * scale;
                osm[n * 68 + d1]       = (acc[mt][nt][2] + b1) * scale;
                osm[(n + 1) * 68 + d1] = (acc[mt][nt][3] + b1) * scale;
            }
        }
        __syncthreads();
        __half* gh = (sel == 0) ? g_Qh : g_Kh;
        __half* gl = (sel == 0) ? g_Ql : g_Kl;
        #pragma unroll
        for (int i = 0; i < 8; i++) {
            int idx = t + 256 * i;
            int n = idx >> 4, q = idx & 15;
            float4 vv = *(const float4*)&osm[n * 68 + 4 * q];
            uint32_t h0 = packhf(vv.x, vv.y), h1 = packhf(vv.z, vv.w);
            float f0, f1, f2, f3;
            uph2(h0, f0, f1); uph2(h1, f2, f3);
            uint32_t l0 = packhf(vv.x - f0, vv.y - f1);
            uint32_t l1 = packhf(vv.z - f2, vv.w - f3);
            size_t o = ((size_t)b * HW_ + n0 + n) * 64 + 4 * q;
            *(uint2*)&gh[o] = make_uint2(h0, h1);
            *(uint2*)&gl[o] = make_uint2(l0, l1);
        }
    }
}

// ---------------------------------------------------------------------------
// HMMA flash attention (fp16). CTA = (b, 256 queries), two 4-warp groups of
// 128 queries each (own Q region + double-buffered K/V, per-group barriers).
// S: 3-term fp16 split. Softmax: online row-max. PV: 1-term.
// (Best-known attn variant — R11 measurement, 184.7 us.)
// ---------------------------------------------------------------------------
#define QG     32768                    // per-group Q (hi 16KB + lo 16KB)
#define BUFSZ  24576
#define KVBASE 65536
#define OFF_KH 0
#define OFF_KL 8192
#define OFF_VH 16384
#define SM_TOTAL (KVBASE + 4 * BUFSZ)   // 163840

__global__ __launch_bounds__(256, 1) void attn_kernel(float* __restrict__ out)
{
    extern __shared__ char smem[];
    const uint32_t sb = smem_u32(smem);
    const int t = threadIdx.x, wid = t >> 5, lane = t & 31;
    const int g = t >> 7;                 // query group (warps 0-3 / 4-7)
    const int tg = t & 127;               // thread-in-group
    const int wg = wid & 3;               // warp-in-group
    const int barid = 1 + g;
    const int b = blockIdx.y, n0 = blockIdx.x * BN + g * 128;

    const __half* Gqh = g_Qh + ((size_t)b * HW_ + n0) * 64;
    const __half* Gql = g_Ql + ((size_t)b * HW_ + n0) * 64;
    const __half* Gkh = g_Kh + (size_t)b * HW_ * 64;
    const __half* Gkl = g_Kl + (size_t)b * HW_ * 64;
    const __half* Gvh = g_Vh + (size_t)b * 64 * HW_;

    const uint32_t qbase = sb + g * QG;

    // Stage this group's Q (128 rows x 128B, hi @0, lo @16384).
    #pragma unroll
    for (int i = 0; i < 16; i++) {
        int cc = tg + 128 * (i & 7);      // 0..1023
        int r = cc >> 3, ch = cc & 7;
        uint32_t dst = qbase + (i >> 3) * 16384 + SWZ128((uint32_t)(r * 128 + ch * 16));
        const __half* src = ((i >= 8) ? Gql : Gqh) + (size_t)r * 64 + ch * 8;
        cpa16(dst, src);
    }
    CP_COMMIT();

    // Prefetch K/V tile 0 into this group's buffer 0 (KH | KL | VH).
    #pragma unroll
    for (int i = 0; i < 12; i++) {
        int c = tg + 128 * i;             // 0..1535
        int seg = c >> 9;
        int cc = c & 511;
        int r = cc >> 3, ch = cc & 7;
        uint32_t dst = sb + KVBASE + (2 * g) * BUFSZ + seg * 8192
                       + SWZ128((uint32_t)(r * 128 + ch * 16));
        const __half* src =
            (seg == 0) ? Gkh + (size_t)r * 64 + ch * 8 :
            (seg == 1) ? Gkl + (size_t)r * 64 + ch * 8 :
                         Gvh + (size_t)r * HW_ + ch * 8;
        cpa16(dst, src);
    }
    CP_COMMIT();

    float o[2][8][4] = {};
    float mrow[2][2] = {{-1e30f, -1e30f}, {-1e30f, -1e30f}};
    float lsum[2][2] = {};

    for (int m0 = 0, tix = 0; m0 < HW_; m0 += BM, tix++) {
        CP_WAIT0();
        BAR_SYNC(barid);

        if (m0 + BM < HW_) {
            uint32_t nb = sb + KVBASE + (2 * g + ((tix + 1) & 1)) * BUFSZ;
            int mn = m0 + BM;
            #pragma unroll
            for (int i = 0; i < 12; i++) {
                int c = tg + 128 * i;
                int seg = c >> 9;
                int cc = c & 511;
                int r = cc >> 3, ch = cc & 7;
                uint32_t dst = nb + seg * 8192 + SWZ128((uint32_t)(r * 128 + ch * 16));
                const __half* src =
                    (seg == 0) ? Gkh + (size_t)(mn + r) * 64 + ch * 8 :
                    (seg == 1) ? Gkl + (size_t)(mn + r) * 64 + ch * 8 :
                                 Gvh + (size_t)r * HW_ + mn + ch * 8;
                cpa16(dst, src);
            }
            CP_COMMIT();
        }

        const uint32_t bufo = sb + KVBASE + (2 * g + (tix & 1)) * BUFSZ;

        // ---- S = Qh*Kh + Qh*Kl + Ql*Kh  (32 rows x 64 keys per warp)
        float s[2][8][4] = {};
        #pragma unroll
        for (int kt = 0; kt < 4; kt++) {
            uint32_t kf[16], lf[16];
            #pragma unroll
            for (int jp = 0; jp < 4; jp++) {
                int krow = 16 * jp + ((lane >> 4) << 3) + (lane & 7);
                uint32_t off = SWZ128((uint32_t)(krow * 128 + kt * 32 + ((lane >> 3) & 1) * 16));
                ldsm4(&kf[4 * jp], bufo + OFF_KH + off);
                ldsm4(&lf[4 * jp], bufo + OFF_KL + off);
            }
            uint32_t qh[2][4], ql[2][4];
            #pragma unroll
            for (int mt = 0; mt < 2; mt++) {
                int qrow = 32 * wg + 16 * mt + (lane & 15);
                uint32_t qoff = SWZ128((uint32_t)(qrow * 128 + kt * 32 + ((lane >> 4) << 4)));
                ldsm4(qh[mt], qbase + qoff);
                ldsm4(ql[mt], qbase + 16384 + qoff);
            }
            #pragma unroll
            for (int mt = 0; mt < 2; mt++)
                #pragma unroll
                for (int j = 0; j < 8; j++) {
                    int ib = (j >> 1) * 4 + (j & 1) * 2;
                    mma_hf(s[mt][j], qh[mt], kf[ib], kf[ib + 1]);
                    mma_hf(s[mt][j], qh[mt], lf[ib], lf[ib + 1]);
                    mma_hf(s[mt][j], ql[mt], kf[ib], kf[ib + 1]);
                }
        }

        // ---- Online row max + rescale of O.
        float mn_[2][2], sc[2][2];
        #pragma unroll
        for (int mt = 0; mt < 2; mt++) {
            float tA = -1e30f, tB = -1e30f;
            #pragma unroll
            for (int j = 0; j < 8; j++) {
                tA = fmaxf(tA, fmaxf(s[mt][j][0], s[mt][j][1]));
                tB = fmaxf(tB, fmaxf(s[mt][j][2], s[mt][j][3]));
            }
            tA = fmaxf(tA, __shfl_xor_sync(0xffffffffu, tA, 1));
            tA = fmaxf(tA, __shfl_xor_sync(0xffffffffu, tA, 2));
            tB = fmaxf(tB, __shfl_xor_sync(0xffffffffu, tB, 1));
            tB = fmaxf(tB, __shfl_xor_sync(0xffffffffu, tB, 2));
            mn_[mt][0] = fmaxf(mrow[mt][0], tA);
            mn_[mt][1] = fmaxf(mrow[mt][1], tB);
            sc[mt][0] = ex2f(mrow[mt][0] - mn_[mt][0]);
            sc[mt][1] = ex2f(mrow[mt][1] - mn_[mt][1]);
            mrow[mt][0] = mn_[mt][0];
            mrow[mt][1] = mn_[mt][1];
            #pragma unroll
            for (int j = 0; j < 8; j++) {
                o[mt][j][0] *= sc[mt][0]; o[mt][j][1] *= sc[mt][0];
                o[mt][j][2] *= sc[mt][1]; o[mt][j][3] *= sc[mt][1];
            }
        }

        // ---- Per 16-key chunk: exponentiate P, then PV MMAs (1-term).
        float ts[2][2] = {};
        #pragma unroll
        for (int kt = 0; kt < 4; kt++) {
            uint32_t vf[16];
            #pragma unroll
            for (int jp = 0; jp < 4; jp++) {
                int vrow = 16 * jp + ((lane >> 4) << 3) + (lane & 7);
                uint32_t off = SWZ128((uint32_t)(vrow * 128 + kt * 32 + ((lane >> 3) & 1) * 16));
                ldsm4(&vf[4 * jp], bufo + OFF_VH + off);
            }
            uint32_t ap[2][4];
            #pragma unroll
            for (int mt = 0; mt < 2; mt++) {
                int j0 = 2 * kt, j1 = 2 * kt + 1;
                float p0 = ex2f(s[mt][j0][0] - mn_[mt][0]), p1 = ex2f(s[mt][j0][1] - mn_[mt][0]);
                float p2 = ex2f(s[mt][j0][2] - mn_[mt][1]), p3 = ex2f(s[mt][j0][3] - mn_[mt][1]);
                float p4 = ex2f(s[mt][j1][0] - mn_[mt][0]), p5 = ex2f(s[mt][j1][1] - mn_[mt][0]);
                float p6 = ex2f(s[mt][j1][2] - mn_[mt][1]), p7 = ex2f(s[mt][j1][3] - mn_[mt][1]);
                ts[mt][0] += (p0 + p1) + (p4 + p5);
                ts[mt][1] += (p2 + p3) + (p6 + p7);
                ap[mt][0] = packhf(p0, p1); ap[mt][1] = packhf(p2, p3);
                ap[mt][2] = packhf(p4, p5); ap[mt][3] = packhf(p6, p7);
            }
            #pragma unroll
            for (int mt = 0; mt < 2; mt++)
                #pragma unroll
                for (int j = 0; j < 8; j++) {
                    int ib = (j >> 1) * 4 + (j & 1) * 2;
                    mma_hf(o[mt][j], ap[mt], vf[ib], vf[ib + 1]);
                }
        }
        #pragma unroll
        for (int mt = 0; mt < 2; mt++) {
            lsum[mt][0] = lsum[mt][0] * sc[mt][0] + ts[mt][0];
            lsum[mt][1] = lsum[mt][1] * sc[mt][1] + ts[mt][1];
        }
    }

    // ---- Row-sum reduction across the quad, normalize.
    float inv[2][2];
    #pragma unroll
    for (int mt = 0; mt < 2; mt++)
        #pragma unroll
        for (int h = 0; h < 2; h++) {
            float l = lsum[mt][h];
            l += __shfl_xor_sync(0xffffffffu, l, 1);
            l += __shfl_xor_sync(0xffffffffu, l, 2);
            inv[mt][h] = 1.0f / l;
        }

    // ---- Stage O[dd][n] in smem (stride 260), then coalesced 8-head stores.
    __syncthreads();   // full-CTA: both groups done with their loops
    float* osm = (float*)smem;
    {
        int ddb = 2 * (lane & 3);
        #pragma unroll
        for (int mt = 0; mt < 2; mt++) {
            int row = g * 128 + 32 * wg + 16 * mt + (lane >> 2);
            #pragma unroll
            for (int j = 0; j < 8; j++) {
                int dd = 8 * j + ddb;
                osm[dd * 260 + row]           = o[mt][j][0] * inv[mt][0];
                osm[(dd + 1) * 260 + row]     = o[mt][j][1] * inv[mt][0];
                osm[dd * 260 + row + 8]       = o[mt][j][2] * inv[mt][1];
                osm[(dd + 1) * 260 + row + 8] = o[mt][j][3] * inv[mt][1];
            }
        }
    }
    __syncthreads();

    float* ob = out + (size_t)b * C_ * HW_ + blockIdx.x * BN;
    #pragma unroll
    for (int i = 0; i < 16; i++) {
        int c = t + 256 * i;              // 0..4095
        int dd = c >> 6, nc = c & 63;
        float4 v = *(const float4*)&osm[dd * 260 + 4 * nc];
        #pragma unroll
        for (int h = 0; h < 8; h++)
            *(float4*)&ob[(size_t)(h * 64 + dd) * HW_ + 4 * nc] = v;
    }
}

// ---------------------------------------------------------------------------
extern "C" void kernel_launch(void* const* d_in, const int* in_sizes, int n_in,
                              void* d_out, int out_size)
{
    (void)in_sizes; (void)n_in; (void)out_size;
    const float* q  = (const float*)d_in[0];
    const float* k  = (const float*)d_in[1];
    const float* v  = (const float*)d_in[2];
    const float* wq = (const float*)d_in[3];
    const float* bq = (const float*)d_in[4];
    const float* wk = (const float*)d_in[5];
    const float* bk = (const float*)d_in[6];
    const float* wv = (const float*)d_in[7];
    const float* bv = (const float*)d_in[8];
    float* out = (float*)d_out;

    const int PROJ_SMEM = 49152;
    cudaFuncSetAttribute(proj_kernel,
                         cudaFuncAttributeMaxDynamicSharedMemorySize, PROJ_SMEM);
    cudaFuncSetAttribute(attn_kernel,
                         cudaFuncAttributeMaxDynamicSharedMemorySize, SM_TOTAL);

    dim3 pgrid(HW_ / 128, B_, 3);
    proj_kernel<<<pgrid, 256, PROJ_SMEM>>>(q, k, v, wq, bq, wk, bk, wv, bv);

    dim3 agrid(HW_ / BN, B_);
    attn_kernel<<<agrid, 256, SM_TOTAL>>>(out);
}

// round 14
// speedup vs baseline: 1.0124x; 1.0124x over previous
#include <cuda_runtime.h>
#include <cuda_fp16.h>
#include <cstdint>

#define B_   8
#define C_   512
#define HW_  4096
#define D_   64
#define BN   256
#define LOG2E 1.4426950408889634f

// Projected operands, fp16 splits.
// Q,K: [b][n][64] row-major (hi+lo). V: [b][dd][HW] d-major (hi only).
__device__ __half g_Qh[(size_t)B_ * HW_ * D_];
__device__ __half g_Ql[(size_t)B_ * HW_ * D_];
__device__ __half g_Kh[(size_t)B_ * HW_ * D_];
__device__ __half g_Kl[(size_t)B_ * HW_ * D_];
__device__ __half g_Vh[(size_t)B_ * D_ * HW_];

__device__ __forceinline__ float ex2f(float x) {
    float y; asm("ex2.approx.ftz.f32 %0, %1;" : "=f"(y) : "f"(x)); return y;
}
// pack two f32 -> f16x2 (lo_val in low half)
__device__ __forceinline__ uint32_t packhf(float lo_val, float hi_val) {
    uint32_t r;
    asm("cvt.rn.f16x2.f32 %0, %1, %2;" : "=r"(r) : "f"(hi_val), "f"(lo_val));
    return r;
}
// unpack f16x2 -> two f32
__device__ __forceinline__ void uph2(uint32_t h, float& lo, float& hi) {
    asm("{ .reg .b16 l, h; mov.b32 {l, h}, %2; cvt.f32.f16 %0, l; cvt.f32.f16 %1, h; }"
        : "=f"(lo), "=f"(hi) : "r"(h));
}
__device__ __forceinline__ uint32_t smem_u32(const void* p) {
    uint32_t a;
    asm("{ .reg .u64 t; cvta.to.shared.u64 t, %1; cvt.u32.u64 %0, t; }"
        : "=r"(a) : "l"(p));
    return a;
}

#define SWZ128(x) ((x) ^ (((x) >> 3) & 0x70))

__device__ __forceinline__ void ldsm4(uint32_t r[4], uint32_t a) {
    asm volatile("ldmatrix.sync.aligned.m8n8.x4.shared.b16 {%0,%1,%2,%3}, [%4];"
        : "=r"(r[0]), "=r"(r[1]), "=r"(r[2]), "=r"(r[3]) : "r"(a));
}
__device__ __forceinline__ void ldsm4t(uint32_t r[4], uint32_t a) {
    asm volatile("ldmatrix.sync.aligned.m8n8.x4.trans.shared.b16 {%0,%1,%2,%3}, [%4];"
        : "=r"(r[0]), "=r"(r[1]), "=r"(r[2]), "=r"(r[3]) : "r"(a));
}
__device__ __forceinline__ void mma_hf(float d[4], const uint32_t a[4],
                                       uint32_t b0, uint32_t b1) {
    asm volatile("mma.sync.aligned.m16n8k16.row.col.f32.f16.f16.f32 "
        "{%0,%1,%2,%3}, {%4,%5,%6,%7}, {%8,%9}, {%0,%1,%2,%3};"
        : "+f"(d[0]), "+f"(d[1]), "+f"(d[2]), "+f"(d[3])
        : "r"(a[0]), "r"(a[1]), "r"(a[2]), "r"(a[3]), "r"(b0), "r"(b1));
}
__device__ __forceinline__ void cpa16(uint32_t s, const void* g) {
    asm volatile("cp.async.cg.shared.global [%0], [%1], 16;" :: "r"(s), "l"(g));
}
#define CP_COMMIT() asm volatile("cp.async.commit_group;" ::: "memory")
#define CP_WAIT0()  asm volatile("cp.async.wait_group 0;" ::: "memory")

// ---------------------------------------------------------------------------
// HMMA projection (z = 0:Q, 1:K, 2:V). D[d][n] = sum_c w[d][c] x[c][n] (+bias).
// fp16-split MMA: 3-term for Q/K, 2-term for V. CTA = 128n x 64d, K=512.
// Next k-step's x/w tiles prefetched into registers during the MMA phase.
// (Best-known proj variant — R11 measurement.)
// ---------------------------------------------------------------------------
__global__ __launch_bounds__(256) void proj_kernel(
    const float* __restrict__ xq, const float* __restrict__ xk, const float* __restrict__ xv,
    const float* __restrict__ wq, const float* __restrict__ bq,
    const float* __restrict__ wk, const float* __restrict__ bk,
    const float* __restrict__ wv, const float* __restrict__ bv)
{
    extern __shared__ char psm[];
    const int sel = blockIdx.z;
    const float* x = (sel == 0) ? xq : (sel == 1) ? xk : xv;
    const float* w = (sel == 0) ? wq : (sel == 1) ? wk : wv;
    const float* bias = (sel == 0) ? bq : (sel == 1) ? bk : bv;

    const int b  = blockIdx.y;
    const int n0 = blockIdx.x * 128;
    const int t  = threadIdx.x, lane = t & 31, wid = t >> 5;
    const int wm = wid >> 2, wn = wid & 3;     // warp grid: 2 (d) x 4 (n)
    const uint32_t sb = smem_u32(psm);

    const float* xb = x + (size_t)b * C_ * HW_ + n0;

    float acc[2][4][4] = {};                   // [mt 16d][nt 8n][frag]

    // Preload k-step 0 into registers.
    float4 xr[8], wr[4];
    #pragma unroll
    for (int i = 0; i < 8; i++) {
        int idx = t + 256 * i;
        int c = idx >> 5, n = (idx & 31) * 4;
        xr[i] = *(const float4*)&xb[(size_t)c * HW_ + n];
    }
    #pragma unroll
    for (int i = 0; i < 4; i++) {
        int idx = t + 256 * i;
        int d = idx >> 4, c = (idx & 15) * 4;
        wr[i] = *(const float4*)&w[(size_t)d * C_ + c];
    }

    for (int kc = 0; kc < C_; kc += 64) {
        __syncthreads();
        // x tile from regs: fp32 -> fp16 h/l, SW128 rows of 64n.
        #pragma unroll
        for (int i = 0; i < 8; i++) {
            int idx = t + 256 * i;
            int c = idx >> 5, n = (idx & 31) * 4;
            float4 xv4 = xr[i];
            uint32_t h0 = packhf(xv4.x, xv4.y), h1 = packhf(xv4.z, xv4.w);
            float f0, f1, f2, f3;
            uph2(h0, f0, f1); uph2(h1, f2, f3);
            uint32_t l0 = packhf(xv4.x - f0, xv4.y - f1);
            uint32_t l1 = packhf(xv4.z - f2, xv4.w - f3);
            int sub = n >> 6, nn = n & 63;
            uint32_t off = (uint32_t)(sub * 8192 + c * 128 + ((nn * 2) ^ ((c & 7) << 4)));
            *(uint2*)(psm + off)         = make_uint2(h0, h1);
            *(uint2*)(psm + 16384 + off) = make_uint2(l0, l1);
        }
        // w tile from regs.
        #pragma unroll
        for (int i = 0; i < 4; i++) {
            int idx = t + 256 * i;
            int d = idx >> 4, c = (idx & 15) * 4;
            float4 wv4 = wr[i];
            uint32_t h0 = packhf(wv4.x, wv4.y), h1 = packhf(wv4.z, wv4.w);
            float f0, f1, f2, f3;
            uph2(h0, f0, f1); uph2(h1, f2, f3);
            uint32_t l0 = packhf(wv4.x - f0, wv4.y - f1);
            uint32_t l1 = packhf(wv4.z - f2, wv4.w - f3);
            uint32_t off = (uint32_t)(d * 128 + ((c * 2) ^ ((d & 7) << 4)));
            *(uint2*)(psm + 32768 + off) = make_uint2(h0, h1);
            *(uint2*)(psm + 40960 + off) = make_uint2(l0, l1);
        }
        // Prefetch next k-step (latency hidden under the MMA phase below).
        if (kc + 64 < C_) {
            #pragma unroll
            for (int i = 0; i < 8; i++) {
                int idx = t + 256 * i;
                int c = idx >> 5, n = (idx & 31) * 4;
                xr[i] = *(const float4*)&xb[(size_t)(kc + 64 + c) * HW_ + n];
            }
            #pragma unroll
            for (int i = 0; i < 4; i++) {
                int idx = t + 256 * i;
                int d = idx >> 4, c = (idx & 15) * 4;
                wr[i] = *(const float4*)&w[(size_t)d * C_ + kc + 64 + c];
            }
        }
        __syncthreads();

        #pragma unroll
        for (int kt = 0; kt < 4; kt++) {
            uint32_t ah[2][4], al[2][4];
            #pragma unroll
            for (int mt = 0; mt < 2; mt++) {
                int row = wm * 32 + mt * 16 + (lane & 15);
                uint32_t off = (uint32_t)(row * 128 +
                    ((kt * 32 + ((lane >> 4) << 4)) ^ ((row & 7) << 4)));
                ldsm4(ah[mt], sb + 32768 + off);
                ldsm4(al[mt], sb + 40960 + off);
            }
            uint32_t bh[8], bl[8];
            #pragma unroll
            for (int hf = 0; hf < 2; hf++) {
                int krow = kt * 16 + (lane & 15);
                int ncol = wn * 32 + hf * 16 + ((lane >> 4) << 3);
                int sub = ncol >> 6, nn = ncol & 63;
                uint32_t off = (uint32_t)(sub * 8192 + krow * 128 +
                    ((nn * 2) ^ ((krow & 7) << 4)));
                ldsm4t(&bh[4 * hf], sb + off);
                ldsm4t(&bl[4 * hf], sb + 16384 + off);
            }
            #pragma unroll
            for (int mt = 0; mt < 2; mt++)
                #pragma unroll
                for (int nt = 0; nt < 4; nt++) {
                    int ib = (nt >> 1) * 4 + (nt & 1) * 2;
                    mma_hf(acc[mt][nt], ah[mt], bh[ib], bh[ib + 1]);
                    mma_hf(acc[mt][nt], ah[mt], bl[ib], bl[ib + 1]);
                    if (sel != 2)
                        mma_hf(acc[mt][nt], al[mt], bh[ib], bh[ib + 1]);
                }
        }
    }

    const int g = lane >> 2, tig = lane & 3;

    if (sel == 2) {
        // V: D[d][n] matches gmem layout -> direct frag stores (hi only).
        #pragma unroll
        for (int mt = 0; mt < 2; mt++) {
            int d0 = wm * 32 + mt * 16 + g, d1 = d0 + 8;
            float b0 = bias[d0], b1 = bias[d1];
            #pragma unroll
            for (int nt = 0; nt < 4; nt++) {
                int n = n0 + wn * 32 + nt * 8 + 2 * tig;
                uint32_t h0 = packhf(acc[mt][nt][0] + b0, acc[mt][nt][1] + b0);
                size_t o0 = ((size_t)b * 64 + d0) * HW_ + n;
                *(uint32_t*)&g_Vh[o0] = h0;
                uint32_t h1 = packhf(acc[mt][nt][2] + b1, acc[mt][nt][3] + b1);
                size_t o1 = ((size_t)b * 64 + d1) * HW_ + n;
                *(uint32_t*)&g_Vh[o1] = h1;
            }
        }
    } else {
        // Q/K: stage D as osm[n][68] fp32, then coalesced [n][64] h/l writes.
        __syncthreads();
        float* osm = (float*)psm;
        const float scale = (sel == 0) ? LOG2E : 1.0f;
        #pragma unroll
        for (int mt = 0; mt < 2; mt++) {
            int d0 = wm * 32 + mt * 16 + g, d1 = d0 + 8;
            float b0 = bias[d0], b1 = bias[d1];
            #pragma unroll
            for (int nt = 0; nt < 4; nt++) {
                int n = wn * 32 + nt * 8 + 2 * tig;
                osm[n * 68 + d0]       = (acc[mt][nt][0] + b0) * scale;
                osm[(n + 1) * 68 + d0] = (acc[mt][nt][1] + b0) * scale;
                osm[n * 68 + d1]       = (acc[mt][nt][2] + b1) * scale;
                osm[(n + 1) * 68 + d1] = (acc[mt][nt][3] + b1) * scale;
            }
        }
        __syncthreads();
        __half* gh = (sel == 0) ? g_Qh : g_Kh;
        __half* gl = (sel == 0) ? g_Ql : g_Kl;
        #pragma unroll
        for (int i = 0; i < 8; i++) {
            int idx = t + 256 * i;
            int n = idx >> 4, q = idx & 15;
            float4 vv = *(const float4*)&osm[n * 68 + 4 * q];
            uint32_t h0 = packhf(vv.x, vv.y), h1 = packhf(vv.z, vv.w);
            float f0, f1, f2, f3;
            uph2(h0, f0, f1); uph2(h1, f2, f3);
            uint32_t l0 = packhf(vv.x - f0, vv.y - f1);
            uint32_t l1 = packhf(vv.z - f2, vv.w - f3);
            size_t o = ((size_t)b * HW_ + n0 + n) * 64 + 4 * q;
            *(uint2*)&gh[o] = make_uint2(h0, h1);
            *(uint2*)&gl[o] = make_uint2(l0, l1);
        }
    }
}

// ---------------------------------------------------------------------------
// HMMA flash attention (fp16). CTA = (b, 256 queries), 8 warps x 32 rows.
// K/V staged in 128-key chunks (two 64-key sub-tiles per chunk): halves the
// CP_WAIT + __syncthreads count vs 64-key staging while keeping the compute
// body, tile order, and numerics identical to the measured-best variant.
// S: 3-term fp16 split. Softmax: online row-max. PV: 1-term.
// Chunk layout (48KB): KH[128rx128B] @0 | KL @16384 | VH sub0 @32768, sub1 @40960.
// ---------------------------------------------------------------------------
#define QBUF   65536
#define CHUNK  49152
#define SM_TOTAL (QBUF + 2 * CHUNK)     // 163840

__global__ __launch_bounds__(256, 1) void attn_kernel(float* __restrict__ out)
{
    extern __shared__ char smem[];
    const uint32_t sb = smem_u32(smem);
    const int t = threadIdx.x, wid = t >> 5, lane = t & 31;
    const int b = blockIdx.y, n0 = blockIdx.x * BN;

    const __half* Gqh = g_Qh + ((size_t)b * HW_ + n0) * 64;
    const __half* Gql = g_Ql + ((size_t)b * HW_ + n0) * 64;
    const __half* Gkh = g_Kh + (size_t)b * HW_ * 64;
    const __half* Gkl = g_Kl + (size_t)b * HW_ * 64;
    const __half* Gvh = g_Vh + (size_t)b * 64 * HW_;

    // Stage Q (256 rows x 128B, hi @0, lo @32768): 16 chunks/thread.
    #pragma unroll
    for (int i = 0; i < 16; i++) {
        int cc = t + 256 * (i & 7);       // 0..2047
        int r = cc >> 3, ch = cc & 7;
        uint32_t dst = sb + (i >> 3) * 32768 + SWZ128((uint32_t)(r * 128 + ch * 16));
        const __half* src = ((i >= 8) ? Gql : Gqh) + (size_t)r * 64 + ch * 8;
        cpa16(dst, src);
    }
    CP_COMMIT();

    // Prefetch K/V chunk 0 (keys 0..127).
    #pragma unroll
    for (int i = 0; i < 12; i++) {
        int c = t + 256 * i;              // 0..3071
        int seg = c >> 10;                // 0:KH 1:KL 2:VH
        int cc = c & 1023;
        uint32_t dst;
        const __half* src;
        if (seg < 2) {
            int r = cc >> 3, ch = cc & 7;
            dst = sb + QBUF + seg * 16384 + SWZ128((uint32_t)(r * 128 + ch * 16));
            src = (seg == 0 ? Gkh : Gkl) + (size_t)r * 64 + ch * 8;
        } else {
            int vsub = cc >> 9, c2 = cc & 511;
            int r = c2 >> 3, ch = c2 & 7;
            dst = sb + QBUF + 32768 + vsub * 8192 + SWZ128((uint32_t)(r * 128 + ch * 16));
            src = Gvh + (size_t)r * HW_ + vsub * 64 + ch * 8;
        }
        cpa16(dst, src);
    }
    CP_COMMIT();

    float o[2][8][4] = {};
    float mrow[2][2] = {{-1e30f, -1e30f}, {-1e30f, -1e30f}};
    float lsum[2][2] = {};

    for (int c0 = 0, tix = 0; c0 < HW_; c0 += 128, tix++) {
        CP_WAIT0();
        __syncthreads();

        if (c0 + 128 < HW_) {
            uint32_t nb = sb + QBUF + ((tix + 1) & 1) * CHUNK;
            int cn = c0 + 128;
            #pragma unroll
            for (int i = 0; i < 12; i++) {
                int c = t + 256 * i;
                int seg = c >> 10;
                int cc = c & 1023;
                uint32_t dst;
                const __half* src;
                if (seg < 2) {
                    int r = cc >> 3, ch = cc & 7;
                    dst = nb + seg * 16384 + SWZ128((uint32_t)(r * 128 + ch * 16));
                    src = (seg == 0 ? Gkh : Gkl) + (size_t)(cn + r) * 64 + ch * 8;
                } else {
                    int vsub = cc >> 9, c2 = cc & 511;
                    int r = c2 >> 3, ch = c2 & 7;
                    dst = nb + 32768 + vsub * 8192 + SWZ128((uint32_t)(r * 128 + ch * 16));
                    src = Gvh + (size_t)r * HW_ + cn + vsub * 64 + ch * 8;
                }
                cpa16(dst, src);
            }
            CP_COMMIT();
        }

        const uint32_t cbase = sb + QBUF + (tix & 1) * CHUNK;

        #pragma unroll
        for (int sub = 0; sub < 2; sub++) {
            const uint32_t kh_b = cbase + sub * 8192;           // 64 key rows
            const uint32_t kl_b = cbase + 16384 + sub * 8192;
            const uint32_t vh_b = cbase + 32768 + sub * 8192;

            // ---- S = Qh*Kh + Qh*Kl + Ql*Kh  (32 rows x 64 keys per warp)
            float s[2][8][4] = {};
            #pragma unroll
            for (int kt = 0; kt < 4; kt++) {
                uint32_t kf[16], lf[16];
                #pragma unroll
                for (int jp = 0; jp < 4; jp++) {
                    int krow = 16 * jp + ((lane >> 4) << 3) + (lane & 7);
                    uint32_t off = SWZ128((uint32_t)(krow * 128 + kt * 32 + ((lane >> 3) & 1) * 16));
                    ldsm4(&kf[4 * jp], kh_b + off);
                    ldsm4(&lf[4 * jp], kl_b + off);
                }
                uint32_t qh[2][4], ql[2][4];
                #pragma unroll
                for (int mt = 0; mt < 2; mt++) {
                    int qrow = 32 * wid + 16 * mt + (lane & 15);
                    uint32_t qoff = SWZ128((uint32_t)(qrow * 128 + kt * 32 + ((lane >> 4) << 4)));
                    ldsm4(qh[mt], sb + qoff);
                    ldsm4(ql[mt], sb + 32768 + qoff);
                }
                #pragma unroll
                for (int mt = 0; mt < 2; mt++)
                    #pragma unroll
                    for (int j = 0; j < 8; j++) {
                        int ib = (j >> 1) * 4 + (j & 1) * 2;
                        mma_hf(s[mt][j], qh[mt], kf[ib], kf[ib + 1]);
                        mma_hf(s[mt][j], qh[mt], lf[ib], lf[ib + 1]);
                        mma_hf(s[mt][j], ql[mt], kf[ib], kf[ib + 1]);
                    }
            }

            // ---- Online row max + rescale of O.
            float mn_[2][2], sc[2][2];
            #pragma unroll
            for (int mt = 0; mt < 2; mt++) {
                float tA = -1e30f, tB = -1e30f;
                #pragma unroll
                for (int j = 0; j < 8; j++) {
                    tA = fmaxf(tA, fmaxf(s[mt][j][0], s[mt][j][1]));
                    tB = fmaxf(tB, fmaxf(s[mt][j][2], s[mt][j][3]));
                }
                tA = fmaxf(tA, __shfl_xor_sync(0xffffffffu, tA, 1));
                tA = fmaxf(tA, __shfl_xor_sync(0xffffffffu, tA, 2));
                tB = fmaxf(tB, __shfl_xor_sync(0xffffffffu, tB, 1));
                tB = fmaxf(tB, __shfl_xor_sync(0xffffffffu, tB, 2));
                mn_[mt][0] = fmaxf(mrow[mt][0], tA);
                mn_[mt][1] = fmaxf(mrow[mt][1], tB);
                sc[mt][0] = ex2f(mrow[mt][0] - mn_[mt][0]);
                sc[mt][1] = ex2f(mrow[mt][1] - mn_[mt][1]);
                mrow[mt][0] = mn_[mt][0];
                mrow[mt][1] = mn_[mt][1];
                #pragma unroll
                for (int j = 0; j < 8; j++) {
                    o[mt][j][0] *= sc[mt][0]; o[mt][j][1] *= sc[mt][0];
                    o[mt][j][2] *= sc[mt][1]; o[mt][j][3] *= sc[mt][1];
                }
            }

            // ---- Per 16-key chunk: exponentiate P, then PV MMAs (1-term).
            float ts[2][2] = {};
            #pragma unroll
            for (int kt = 0; kt < 4; kt++) {
                uint32_t vf[16];
                #pragma unroll
                for (int jp = 0; jp < 4; jp++) {
                    int vrow = 16 * jp + ((lane >> 4) << 3) + (lane & 7);
                    uint32_t off = SWZ128((uint32_t)(vrow * 128 + kt * 32 + ((lane >> 3) & 1) * 16));
                    ldsm4(&vf[4 * jp], vh_b + off);
                }
                uint32_t ap[2][4];
                #pragma unroll
                for (int mt = 0; mt < 2; mt++) {
                    int j0 = 2 * kt, j1 = 2 * kt + 1;
                    float p0 = ex2f(s[mt][j0][0] - mn_[mt][0]), p1 = ex2f(s[mt][j0][1] - mn_[mt][0]);
                    float p2 = ex2f(s[mt][j0][2] - mn_[mt][1]), p3 = ex2f(s[mt][j0][3] - mn_[mt][1]);
                    float p4 = ex2f(s[mt][j1][0] - mn_[mt][0]), p5 = ex2f(s[mt][j1][1] - mn_[mt][0]);
                    float p6 = ex2f(s[mt][j1][2] - mn_[mt][1]), p7 = ex2f(s[mt][j1][3] - mn_[mt][1]);
                    ts[mt][0] += (p0 + p1) + (p4 + p5);
                    ts[mt][1] += (p2 + p3) + (p6 + p7);
                    ap[mt][0] = packhf(p0, p1); ap[mt][1] = packhf(p2, p3);
                    ap[mt][2] = packhf(p4, p5); ap[mt][3] = packhf(p6, p7);
                }
                #pragma unroll
                for (int mt = 0; mt < 2; mt++)
                    #pragma unroll
                    for (int j = 0; j < 8; j++) {
                        int ib = (j >> 1) * 4 + (j & 1) * 2;
                        mma_hf(o[mt][j], ap[mt], vf[ib], vf[ib + 1]);
                    }
            }
            #pragma unroll
            for (int mt = 0; mt < 2; mt++) {
                lsum[mt][0] = lsum[mt][0] * sc[mt][0] + ts[mt][0];
                lsum[mt][1] = lsum[mt][1] * sc[mt][1] + ts[mt][1];
            }
        }
    }

    // ---- Row-sum reduction across the quad, normalize.
    float inv[2][2];
    #pragma unroll
    for (int mt = 0; mt < 2; mt++)
        #pragma unroll
        for (int h = 0; h < 2; h++) {
            float l = lsum[mt][h];
            l += __shfl_xor_sync(0xffffffffu, l, 1);
            l += __shfl_xor_sync(0xffffffffu, l, 2);
            inv[mt][h] = 1.0f / l;
        }

    // ---- Stage O[dd][n] in smem (stride 260), then coalesced 8-head stores.
    __syncthreads();
    float* osm = (float*)smem;
    {
        int ddb = 2 * (lane & 3);
        #pragma unroll
        for (int mt = 0; mt < 2; mt++) {
            int row = 32 * wid + 16 * mt + (lane >> 2);
            #pragma unroll
            for (int j = 0; j < 8; j++) {
                int dd = 8 * j + ddb;
                osm[dd * 260 + row]           = o[mt][j][0] * inv[mt][0];
                osm[(dd + 1) * 260 + row]     = o[mt][j][1] * inv[mt][0];
                osm[dd * 260 + row + 8]       = o[mt][j][2] * inv[mt][1];
                osm[(dd + 1) * 260 + row + 8] = o[mt][j][3] * inv[mt][1];
            }
        }
    }
    __syncthreads();

    float* ob = out + (size_t)b * C_ * HW_ + n0;
    #pragma unroll
    for (int i = 0; i < 16; i++) {
        int c = t + 256 * i;              // 0..4095
        int dd = c >> 6, nc = c & 63;
        float4 v = *(const float4*)&osm[dd * 260 + 4 * nc];
        #pragma unroll
        for (int h = 0; h < 8; h++)
            *(float4*)&ob[(size_t)(h * 64 + dd) * HW_ + 4 * nc] = v;
    }
}

// ---------------------------------------------------------------------------
extern "C" void kernel_launch(void* const* d_in, const int* in_sizes, int n_in,
                              void* d_out, int out_size)
{
    (void)in_sizes; (void)n_in; (void)out_size;
    const float* q  = (const float*)d_in[0];
    const float* k  = (const float*)d_in[1];
    const float* v  = (const float*)d_in[2];
    const float* wq = (const float*)d_in[3];
    const float* bq = (const float*)d_in[4];
    const float* wk = (const float*)d_in[5];
    const float* bk = (const float*)d_in[6];
    const float* wv = (const float*)d_in[7];
    const float* bv = (const float*)d_in[8];
    float* out = (float*)d_out;

    const int PROJ_SMEM = 49152;
    cudaFuncSetAttribute(proj_kernel,
                         cudaFuncAttributeMaxDynamicSharedMemorySize, PROJ_SMEM);
    cudaFuncSetAttribute(attn_kernel,
                         cudaFuncAttributeMaxDynamicSharedMemorySize, SM_TOTAL);

    dim3 pgrid(HW_ / 128, B_, 3);
    proj_kernel<<<pgrid, 256, PROJ_SMEM>>>(q, k, v, wq, bq, wk, bk, wv, bv);

    dim3 agrid(HW_ / BN, B_);
    attn_kernel<<<agrid, 256, SM_TOTAL>>>(out);
}

// round 15
// speedup vs baseline: 1.0278x; 1.0151x over previous
#include <cuda_runtime.h>
#include <cuda_fp16.h>
#include <cstdint>

#define B_   8
#define C_   512
#define HW_  4096
#define D_   64
#define BN   256
#define BM   64
#define LOG2E 1.4426950408889634f

// Projected operands, fp16 splits.
// Q,K: [b][n][64] row-major (hi+lo). V: [b][dd][HW] d-major (hi only).
__device__ __half g_Qh[(size_t)B_ * HW_ * D_];
__device__ __half g_Ql[(size_t)B_ * HW_ * D_];
__device__ __half g_Kh[(size_t)B_ * HW_ * D_];
__device__ __half g_Kl[(size_t)B_ * HW_ * D_];
__device__ __half g_Vh[(size_t)B_ * D_ * HW_];

__device__ __forceinline__ float ex2f(float x) {
    float y; asm("ex2.approx.ftz.f32 %0, %1;" : "=f"(y) : "f"(x)); return y;
}
// packed fp16x2 exp2 (one MUFU op per pair)
__device__ __forceinline__ uint32_t ex2h2(uint32_t x) {
    uint32_t y; asm("ex2.approx.f16x2 %0, %1;" : "=r"(y) : "r"(x)); return y;
}
// pack two f32 -> f16x2 (lo_val in low half)
__device__ __forceinline__ uint32_t packhf(float lo_val, float hi_val) {
    uint32_t r;
    asm("cvt.rn.f16x2.f32 %0, %1, %2;" : "=r"(r) : "f"(hi_val), "f"(lo_val));
    return r;
}
// unpack f16x2 -> two f32
__device__ __forceinline__ void uph2(uint32_t h, float& lo, float& hi) {
    asm("{ .reg .b16 l, h; mov.b32 {l, h}, %2; cvt.f32.f16 %0, l; cvt.f32.f16 %1, h; }"
        : "=f"(lo), "=f"(hi) : "r"(h));
}
__device__ __forceinline__ uint32_t smem_u32(const void* p) {
    uint32_t a;
    asm("{ .reg .u64 t; cvta.to.shared.u64 t, %1; cvt.u32.u64 %0, t; }"
        : "=r"(a) : "l"(p));
    return a;
}

#define SWZ128(x) ((x) ^ (((x) >> 3) & 0x70))

__device__ __forceinline__ void ldsm4(uint32_t r[4], uint32_t a) {
    asm volatile("ldmatrix.sync.aligned.m8n8.x4.shared.b16 {%0,%1,%2,%3}, [%4];"
        : "=r"(r[0]), "=r"(r[1]), "=r"(r[2]), "=r"(r[3]) : "r"(a));
}
__device__ __forceinline__ void ldsm4t(uint32_t r[4], uint32_t a) {
    asm volatile("ldmatrix.sync.aligned.m8n8.x4.trans.shared.b16 {%0,%1,%2,%3}, [%4];"
        : "=r"(r[0]), "=r"(r[1]), "=r"(r[2]), "=r"(r[3]) : "r"(a));
}
__device__ __forceinline__ void mma_hf(float d[4], const uint32_t a[4],
                                       uint32_t b0, uint32_t b1) {
    asm volatile("mma.sync.aligned.m16n8k16.row.col.f32.f16.f16.f32 "
        "{%0,%1,%2,%3}, {%4,%5,%6,%7}, {%8,%9}, {%0,%1,%2,%3};"
        : "+f"(d[0]), "+f"(d[1]), "+f"(d[2]), "+f"(d[3])
        : "r"(a[0]), "r"(a[1]), "r"(a[2]), "r"(a[3]), "r"(b0), "r"(b1));
}
__device__ __forceinline__ void cpa16(uint32_t s, const void* g) {
    asm volatile("cp.async.cg.shared.global [%0], [%1], 16;" :: "r"(s), "l"(g));
}
#define CP_COMMIT() asm volatile("cp.async.commit_group;" ::: "memory")
#define CP_WAIT0()  asm volatile("cp.async.wait_group 0;" ::: "memory")
#define BAR_SYNC(id) asm volatile("bar.sync %0, 128;" :: "r"(id) : "memory")

// ---------------------------------------------------------------------------
// HMMA projection (z = 0:Q, 1:K, 2:V). D[d][n] = sum_c w[d][c] x[c][n] (+bias).
// fp16-split MMA: 3-term for Q/K, 2-term for V. CTA = 128n x 64d, K=512.
// Next k-step's x/w tiles prefetched into registers during the MMA phase.
// (Best-known proj variant — R14 measurement, 65.3 us.)
// ---------------------------------------------------------------------------
__global__ __launch_bounds__(256) void proj_kernel(
    const float* __restrict__ xq, const float* __restrict__ xk, const float* __restrict__ xv,
    const float* __restrict__ wq, const float* __restrict__ bq,
    const float* __restrict__ wk, const float* __restrict__ bk,
    const float* __restrict__ wv, const float* __restrict__ bv)
{
    extern __shared__ char psm[];
    const int sel = blockIdx.z;
    const float* x = (sel == 0) ? xq : (sel == 1) ? xk : xv;
    const float* w = (sel == 0) ? wq : (sel == 1) ? wk : wv;
    const float* bias = (sel == 0) ? bq : (sel == 1) ? bk : bv;

    const int b  = blockIdx.y;
    const int n0 = blockIdx.x * 128;
    const int t  = threadIdx.x, lane = t & 31, wid = t >> 5;
    const int wm = wid >> 2, wn = wid & 3;     // warp grid: 2 (d) x 4 (n)
    const uint32_t sb = smem_u32(psm);

    const float* xb = x + (size_t)b * C_ * HW_ + n0;

    float acc[2][4][4] = {};                   // [mt 16d][nt 8n][frag]

    // Preload k-step 0 into registers.
    float4 xr[8], wr[4];
    #pragma unroll
    for (int i = 0; i < 8; i++) {
        int idx = t + 256 * i;
        int c = idx >> 5, n = (idx & 31) * 4;
        xr[i] = *(const float4*)&xb[(size_t)c * HW_ + n];
    }
    #pragma unroll
    for (int i = 0; i < 4; i++) {
        int idx = t + 256 * i;
        int d = idx >> 4, c = (idx & 15) * 4;
        wr[i] = *(const float4*)&w[(size_t)d * C_ + c];
    }

    for (int kc = 0; kc < C_; kc += 64) {
        __syncthreads();
        // x tile from regs: fp32 -> fp16 h/l, SW128 rows of 64n.
        #pragma unroll
        for (int i = 0; i < 8; i++) {
            int idx = t + 256 * i;
            int c = idx >> 5, n = (idx & 31) * 4;
            float4 xv4 = xr[i];
            uint32_t h0 = packhf(xv4.x, xv4.y), h1 = packhf(xv4.z, xv4.w);
            float f0, f1, f2, f3;
            uph2(h0, f0, f1); uph2(h1, f2, f3);
            uint32_t l0 = packhf(xv4.x - f0, xv4.y - f1);
            uint32_t l1 = packhf(xv4.z - f2, xv4.w - f3);
            int sub = n >> 6, nn = n & 63;
            uint32_t off = (uint32_t)(sub * 8192 + c * 128 + ((nn * 2) ^ ((c & 7) << 4)));
            *(uint2*)(psm + off)         = make_uint2(h0, h1);
            *(uint2*)(psm + 16384 + off) = make_uint2(l0, l1);
        }
        // w tile from regs.
        #pragma unroll
        for (int i = 0; i < 4; i++) {
            int idx = t + 256 * i;
            int d = idx >> 4, c = (idx & 15) * 4;
            float4 wv4 = wr[i];
            uint32_t h0 = packhf(wv4.x, wv4.y), h1 = packhf(wv4.z, wv4.w);
            float f0, f1, f2, f3;
            uph2(h0, f0, f1); uph2(h1, f2, f3);
            uint32_t l0 = packhf(wv4.x - f0, wv4.y - f1);
            uint32_t l1 = packhf(wv4.z - f2, wv4.w - f3);
            uint32_t off = (uint32_t)(d * 128 + ((c * 2) ^ ((d & 7) << 4)));
            *(uint2*)(psm + 32768 + off) = make_uint2(h0, h1);
            *(uint2*)(psm + 40960 + off) = make_uint2(l0, l1);
        }
        // Prefetch next k-step (latency hidden under the MMA phase below).
        if (kc + 64 < C_) {
            #pragma unroll
            for (int i = 0; i < 8; i++) {
                int idx = t + 256 * i;
                int c = idx >> 5, n = (idx & 31) * 4;
                xr[i] = *(const float4*)&xb[(size_t)(kc + 64 + c) * HW_ + n];
            }
            #pragma unroll
            for (int i = 0; i < 4; i++) {
                int idx = t + 256 * i;
                int d = idx >> 4, c = (idx & 15) * 4;
                wr[i] = *(const float4*)&w[(size_t)d * C_ + kc + 64 + c];
            }
        }
        __syncthreads();

        #pragma unroll
        for (int kt = 0; kt < 4; kt++) {
            uint32_t ah[2][4], al[2][4];
            #pragma unroll
            for (int mt = 0; mt < 2; mt++) {
                int row = wm * 32 + mt * 16 + (lane & 15);
                uint32_t off = (uint32_t)(row * 128 +
                    ((kt * 32 + ((lane >> 4) << 4)) ^ ((row & 7) << 4)));
                ldsm4(ah[mt], sb + 32768 + off);
                ldsm4(al[mt], sb + 40960 + off);
            }
            uint32_t bh[8], bl[8];
            #pragma unroll
            for (int hf = 0; hf < 2; hf++) {
                int krow = kt * 16 + (lane & 15);
                int ncol = wn * 32 + hf * 16 + ((lane >> 4) << 3);
                int sub = ncol >> 6, nn = ncol & 63;
                uint32_t off = (uint32_t)(sub * 8192 + krow * 128 +
                    ((nn * 2) ^ ((krow & 7) << 4)));
                ldsm4t(&bh[4 * hf], sb + off);
                ldsm4t(&bl[4 * hf], sb + 16384 + off);
            }
            #pragma unroll
            for (int mt = 0; mt < 2; mt++)
                #pragma unroll
                for (int nt = 0; nt < 4; nt++) {
                    int ib = (nt >> 1) * 4 + (nt & 1) * 2;
                    mma_hf(acc[mt][nt], ah[mt], bh[ib], bh[ib + 1]);
                    mma_hf(acc[mt][nt], ah[mt], bl[ib], bl[ib + 1]);
                    if (sel != 2)
                        mma_hf(acc[mt][nt], al[mt], bh[ib], bh[ib + 1]);
                }
        }
    }

    const int g = lane >> 2, tig = lane & 3;

    if (sel == 2) {
        // V: D[d][n] matches gmem layout -> direct frag stores (hi only).
        #pragma unroll
        for (int mt = 0; mt < 2; mt++) {
            int d0 = wm * 32 + mt * 16 + g, d1 = d0 + 8;
            float b0 = bias[d0], b1 = bias[d1];
            #pragma unroll
            for (int nt = 0; nt < 4; nt++) {
                int n = n0 + wn * 32 + nt * 8 + 2 * tig;
                uint32_t h0 = packhf(acc[mt][nt][0] + b0, acc[mt][nt][1] + b0);
                size_t o0 = ((size_t)b * 64 + d0) * HW_ + n;
                *(uint32_t*)&g_Vh[o0] = h0;
                uint32_t h1 = packhf(acc[mt][nt][2] + b1, acc[mt][nt][3] + b1);
                size_t o1 = ((size_t)b * 64 + d1) * HW_ + n;
                *(uint32_t*)&g_Vh[o1] = h1;
            }
        }
    } else {
        // Q/K: stage D as osm[n][68] fp32, then coalesced [n][64] h/l writes.
        __syncthreads();
        float* osm = (float*)psm;
        const float scale = (sel == 0) ? LOG2E : 1.0f;
        #pragma unroll
        for (int mt = 0; mt < 2; mt++) {
            int d0 = wm * 32 + mt * 16 + g, d1 = d0 + 8;
            float b0 = bias[d0], b1 = bias[d1];
            #pragma unroll
            for (int nt = 0; nt < 4; nt++) {
                int n = wn * 32 + nt * 8 + 2 * tig;
                osm[n * 68 + d0]       = (acc[mt][nt][0] + b0) * scale;
                osm[(n + 1) * 68 + d0] = (acc[mt][nt][1] + b0) * scale;
                osm[n * 68 + d1]       = (acc[mt][nt][2] + b1) * scale;
                osm[(n + 1) * 68 + d1] = (acc[mt][nt][3] + b1) * scale;
            }
        }
        __syncthreads();
        __half* gh = (sel == 0) ? g_Qh : g_Kh;
        __half* gl = (sel == 0) ? g_Ql : g_Kl;
        #pragma unroll
        for (int i = 0; i < 8; i++) {
            int idx = t + 256 * i;
            int n = idx >> 4, q = idx & 15;
            float4 vv = *(const float4*)&osm[n * 68 + 4 * q];
            uint32_t h0 = packhf(vv.x, vv.y), h1 = packhf(vv.z, vv.w);
            float f0, f1, f2, f3;
            uph2(h0, f0, f1); uph2(h1, f2, f3);
            uint32_t l0 = packhf(vv.x - f0, vv.y - f1);
            uint32_t l1 = packhf(vv.z - f2, vv.w - f3);
            size_t o = ((size_t)b * HW_ + n0 + n) * 64 + 4 * q;
            *(uint2*)&gh[o] = make_uint2(h0, h1);
            *(uint2*)&gl[o] = make_uint2(l0, l1);
        }
    }
}

// ---------------------------------------------------------------------------
// HMMA flash attention (fp16). CTA = (b, 256 queries), two 4-warp groups of
// 128 queries each (own Q region + double-buffered K/V, per-group barriers).
// S: 3-term fp16 split. Softmax: online row-max with PACKED fp16x2 exp2
// (halves the MUFU op count; lsum accumulated fp32 from the same fp16 p
// values that feed the PV MMA). PV: 1-term.
// ---------------------------------------------------------------------------
#define QG     32768                    // per-group Q (hi 16KB + lo 16KB)
#define BUFSZ  24576
#define KVBASE 65536
#define OFF_KH 0
#define OFF_KL 8192
#define OFF_VH 16384
#define SM_TOTAL (KVBASE + 4 * BUFSZ)   // 163840

__global__ __launch_bounds__(256, 1) void attn_kernel(float* __restrict__ out)
{
    extern __shared__ char smem[];
    const uint32_t sb = smem_u32(smem);
    const int t = threadIdx.x, wid = t >> 5, lane = t & 31;
    const int g = t >> 7;                 // query group (warps 0-3 / 4-7)
    const int tg = t & 127;               // thread-in-group
    const int wg = wid & 3;               // warp-in-group
    const int barid = 1 + g;
    const int b = blockIdx.y, n0 = blockIdx.x * BN + g * 128;

    const __half* Gqh = g_Qh + ((size_t)b * HW_ + n0) * 64;
    const __half* Gql = g_Ql + ((size_t)b * HW_ + n0) * 64;
    const __half* Gkh = g_Kh + (size_t)b * HW_ * 64;
    const __half* Gkl = g_Kl + (size_t)b * HW_ * 64;
    const __half* Gvh = g_Vh + (size_t)b * 64 * HW_;

    const uint32_t qbase = sb + g * QG;

    // Stage this group's Q (128 rows x 128B, hi @0, lo @16384).
    #pragma unroll
    for (int i = 0; i < 16; i++) {
        int cc = tg + 128 * (i & 7);      // 0..1023
        int r = cc >> 3, ch = cc & 7;
        uint32_t dst = qbase + (i >> 3) * 16384 + SWZ128((uint32_t)(r * 128 + ch * 16));
        const __half* src = ((i >= 8) ? Gql : Gqh) + (size_t)r * 64 + ch * 8;
        cpa16(dst, src);
    }
    CP_COMMIT();

    // Prefetch K/V tile 0 into this group's buffer 0 (KH | KL | VH).
    #pragma unroll
    for (int i = 0; i < 12; i++) {
        int c = tg + 128 * i;             // 0..1535
        int seg = c >> 9;
        int cc = c & 511;
        int r = cc >> 3, ch = cc & 7;
        uint32_t dst = sb + KVBASE + (2 * g) * BUFSZ + seg * 8192
                       + SWZ128((uint32_t)(r * 128 + ch * 16));
        const __half* src =
            (seg == 0) ? Gkh + (size_t)r * 64 + ch * 8 :
            (seg == 1) ? Gkl + (size_t)r * 64 + ch * 8 :
                         Gvh + (size_t)r * HW_ + ch * 8;
        cpa16(dst, src);
    }
    CP_COMMIT();

    float o[2][8][4] = {};
    float mrow[2][2] = {{-1e30f, -1e30f}, {-1e30f, -1e30f}};
    float lsum[2][2] = {};

    for (int m0 = 0, tix = 0; m0 < HW_; m0 += BM, tix++) {
        CP_WAIT0();
        BAR_SYNC(barid);

        if (m0 + BM < HW_) {
            uint32_t nb = sb + KVBASE + (2 * g + ((tix + 1) & 1)) * BUFSZ;
            int mn = m0 + BM;
            #pragma unroll
            for (int i = 0; i < 12; i++) {
                int c = tg + 128 * i;
                int seg = c >> 9;
                int cc = c & 511;
                int r = cc >> 3, ch = cc & 7;
                uint32_t dst = nb + seg * 8192 + SWZ128((uint32_t)(r * 128 + ch * 16));
                const __half* src =
                    (seg == 0) ? Gkh + (size_t)(mn + r) * 64 + ch * 8 :
                    (seg == 1) ? Gkl + (size_t)(mn + r) * 64 + ch * 8 :
                                 Gvh + (size_t)r * HW_ + mn + ch * 8;
                cpa16(dst, src);
            }
            CP_COMMIT();
        }

        const uint32_t bufo = sb + KVBASE + (2 * g + (tix & 1)) * BUFSZ;

        // ---- S = Qh*Kh + Qh*Kl + Ql*Kh  (32 rows x 64 keys per warp)
        float s[2][8][4] = {};
        #pragma unroll
        for (int kt = 0; kt < 4; kt++) {
            uint32_t kf[16], lf[16];
            #pragma unroll
            for (int jp = 0; jp < 4; jp++) {
                int krow = 16 * jp + ((lane >> 4) << 3) + (lane & 7);
                uint32_t off = SWZ128((uint32_t)(krow * 128 + kt * 32 + ((lane >> 3) & 1) * 16));
                ldsm4(&kf[4 * jp], bufo + OFF_KH + off);
                ldsm4(&lf[4 * jp], bufo + OFF_KL + off);
            }
            uint32_t qh[2][4], ql[2][4];
            #pragma unroll
            for (int mt = 0; mt < 2; mt++) {
                int qrow = 32 * wg + 16 * mt + (lane & 15);
                uint32_t qoff = SWZ128((uint32_t)(qrow * 128 + kt * 32 + ((lane >> 4) << 4)));
                ldsm4(qh[mt], qbase + qoff);
                ldsm4(ql[mt], qbase + 16384 + qoff);
            }
            #pragma unroll
            for (int mt = 0; mt < 2; mt++)
                #pragma unroll
                for (int j = 0; j < 8; j++) {
                    int ib = (j >> 1) * 4 + (j & 1) * 2;
                    mma_hf(s[mt][j], qh[mt], kf[ib], kf[ib + 1]);
                    mma_hf(s[mt][j], qh[mt], lf[ib], lf[ib + 1]);
                    mma_hf(s[mt][j], ql[mt], kf[ib], kf[ib + 1]);
                }
        }

        // ---- Online row max + rescale of O.
        float mn_[2][2], sc[2][2];
        #pragma unroll
        for (int mt = 0; mt < 2; mt++) {
            float tA = -1e30f, tB = -1e30f;
            #pragma unroll
            for (int j = 0; j < 8; j++) {
                tA = fmaxf(tA, fmaxf(s[mt][j][0], s[mt][j][1]));
                tB = fmaxf(tB, fmaxf(s[mt][j][2], s[mt][j][3]));
            }
            tA = fmaxf(tA, __shfl_xor_sync(0xffffffffu, tA, 1));
            tA = fmaxf(tA, __shfl_xor_sync(0xffffffffu, tA, 2));
            tB = fmaxf(tB, __shfl_xor_sync(0xffffffffu, tB, 1));
            tB = fmaxf(tB, __shfl_xor_sync(0xffffffffu, tB, 2));
            mn_[mt][0] = fmaxf(mrow[mt][0], tA);
            mn_[mt][1] = fmaxf(mrow[mt][1], tB);
            sc[mt][0] = ex2f(mrow[mt][0] - mn_[mt][0]);
            sc[mt][1] = ex2f(mrow[mt][1] - mn_[mt][1]);
            mrow[mt][0] = mn_[mt][0];
            mrow[mt][1] = mn_[mt][1];
            #pragma unroll
            for (int j = 0; j < 8; j++) {
                o[mt][j][0] *= sc[mt][0]; o[mt][j][1] *= sc[mt][0];
                o[mt][j][2] *= sc[mt][1]; o[mt][j][3] *= sc[mt][1];
            }
        }

        // ---- Per 16-key chunk: packed fp16x2 exp2, then PV MMAs (1-term).
        float ts[2][2] = {};
        #pragma unroll
        for (int kt = 0; kt < 4; kt++) {
            uint32_t vf[16];
            #pragma unroll
            for (int jp = 0; jp < 4; jp++) {
                int vrow = 16 * jp + ((lane >> 4) << 3) + (lane & 7);
                uint32_t off = SWZ128((uint32_t)(vrow * 128 + kt * 32 + ((lane >> 3) & 1) * 16));
                ldsm4(&vf[4 * jp], bufo + OFF_VH + off);
            }
            uint32_t ap[2][4];
            #pragma unroll
            for (int mt = 0; mt < 2; mt++) {
                int j0 = 2 * kt, j1 = 2 * kt + 1;
                // pack deltas into f16x2 and exponentiate pairwise
                uint32_t d0 = packhf(s[mt][j0][0] - mn_[mt][0], s[mt][j0][1] - mn_[mt][0]);
                uint32_t d1 = packhf(s[mt][j0][2] - mn_[mt][1], s[mt][j0][3] - mn_[mt][1]);
                uint32_t d2 = packhf(s[mt][j1][0] - mn_[mt][0], s[mt][j1][1] - mn_[mt][0]);
                uint32_t d3 = packhf(s[mt][j1][2] - mn_[mt][1], s[mt][j1][3] - mn_[mt][1]);
                uint32_t p0 = ex2h2(d0), p1 = ex2h2(d1);
                uint32_t p2 = ex2h2(d2), p3 = ex2h2(d3);
                ap[mt][0] = p0; ap[mt][1] = p1; ap[mt][2] = p2; ap[mt][3] = p3;
                // fp32 lsum from the SAME fp16 p values used in PV
                float ua, ub;
                uph2(p0, ua, ub); ts[mt][0] += ua + ub;
                uph2(p1, ua, ub); ts[mt][1] += ua + ub;
                uph2(p2, ua, ub); ts[mt][0] += ua + ub;
                uph2(p3, ua, ub); ts[mt][1] += ua + ub;
            }
            #pragma unroll
            for (int mt = 0; mt < 2; mt++)
                #pragma unroll
                for (int j = 0; j < 8; j++) {
                    int ib = (j >> 1) * 4 + (j & 1) * 2;
                    mma_hf(o[mt][j], ap[mt], vf[ib], vf[ib + 1]);
                }
        }
        #pragma unroll
        for (int mt = 0; mt < 2; mt++) {
            lsum[mt][0] = lsum[mt][0] * sc[mt][0] + ts[mt][0];
            lsum[mt][1] = lsum[mt][1] * sc[mt][1] + ts[mt][1];
        }
    }

    // ---- Row-sum reduction across the quad, normalize.
    float inv[2][2];
    #pragma unroll
    for (int mt = 0; mt < 2; mt++)
        #pragma unroll
        for (int h = 0; h < 2; h++) {
            float l = lsum[mt][h];
            l += __shfl_xor_sync(0xffffffffu, l, 1);
            l += __shfl_xor_sync(0xffffffffu, l, 2);
            inv[mt][h] = 1.0f / l;
        }

    // ---- Stage O[dd][n] in smem (stride 260), then coalesced 8-head stores.
    __syncthreads();   // full-CTA: both groups done with their loops
    float* osm = (float*)smem;
    {
        int ddb = 2 * (lane & 3);
        #pragma unroll
        for (int mt = 0; mt < 2; mt++) {
            int row = g * 128 + 32 * wg + 16 * mt + (lane >> 2);
            #pragma unroll
            for (int j = 0; j < 8; j++) {
                int dd = 8 * j + ddb;
                osm[dd * 260 + row]           = o[mt][j][0] * inv[mt][0];
                osm[(dd + 1) * 260 + row]     = o[mt][j][1] * inv[mt][0];
                osm[dd * 260 + row + 8]       = o[mt][j][2] * inv[mt][1];
                osm[(dd + 1) * 260 + row + 8] = o[mt][j][3] * inv[mt][1];
            }
        }
    }
    __syncthreads();

    float* ob = out + (size_t)b * C_ * HW_ + blockIdx.x * BN;
    #pragma unroll
    for (int i = 0; i < 16; i++) {
        int c = t + 256 * i;              // 0..4095
        int dd = c >> 6, nc = c & 63;
        float4 v = *(const float4*)&osm[dd * 260 + 4 * nc];
        #pragma unroll
        for (int h = 0; h < 8; h++)
            *(float4*)&ob[(size_t)(h * 64 + dd) * HW_ + 4 * nc] = v;
    }
}

// ---------------------------------------------------------------------------
extern "C" void kernel_launch(void* const* d_in, const int* in_sizes, int n_in,
                              void* d_out, int out_size)
{
    (void)in_sizes; (void)n_in; (void)out_size;
    const float* q  = (const float*)d_in[0];
    const float* k  = (const float*)d_in[1];
    const float* v  = (const float*)d_in[2];
    const float* wq = (const float*)d_in[3];
    const float* bq = (const float*)d_in[4];
    const float* wk = (const float*)d_in[5];
    const float* bk = (const float*)d_in[6];
    const float* wv = (const float*)d_in[7];
    const float* bv = (const float*)d_in[8];
    float* out = (float*)d_out;

    const int PROJ_SMEM = 49152;
    cudaFuncSetAttribute(proj_kernel,
                         cudaFuncAttributeMaxDynamicSharedMemorySize, PROJ_SMEM);
    cudaFuncSetAttribute(attn_kernel,
                         cudaFuncAttributeMaxDynamicSharedMemorySize, SM_TOTAL);

    dim3 pgrid(HW_ / 128, B_, 3);
    proj_kernel<<<pgrid, 256, PROJ_SMEM>>>(q, k, v, wq, bq, wk, bk, wv, bv);

    dim3 agrid(HW_ / BN, B_);
    attn_kernel<<<agrid, 256, SM_TOTAL>>>(out);
}

// round 16
// speedup vs baseline: 1.2203x; 1.1874x over previous
#include <cuda_runtime.h>
#include <cuda_fp16.h>
#include <cstdint>

#define B_   8
#define C_   512
#define HW_  4096
#define D_   64
#define BN   256
#define BM   64
#define LOG2E 1.4426950408889634f

// Projected operands, fp16.
// Q: [b][n][64] hi only. K: [b][n][64] hi+lo. V: [b][dd][HW] hi only.
__device__ __half g_Qh[(size_t)B_ * HW_ * D_];
__device__ __half g_Kh[(size_t)B_ * HW_ * D_];
__device__ __half g_Kl[(size_t)B_ * HW_ * D_];
__device__ __half g_Vh[(size_t)B_ * D_ * HW_];

__device__ __forceinline__ float ex2f(float x) {
    float y; asm("ex2.approx.ftz.f32 %0, %1;" : "=f"(y) : "f"(x)); return y;
}
// pack two f32 -> f16x2 (lo_val in low half)
__device__ __forceinline__ uint32_t packhf(float lo_val, float hi_val) {
    uint32_t r;
    asm("cvt.rn.f16x2.f32 %0, %1, %2;" : "=r"(r) : "f"(hi_val), "f"(lo_val));
    return r;
}
// unpack f16x2 -> two f32
__device__ __forceinline__ void uph2(uint32_t h, float& lo, float& hi) {
    asm("{ .reg .b16 l, h; mov.b32 {l, h}, %2; cvt.f32.f16 %0, l; cvt.f32.f16 %1, h; }"
        : "=f"(lo), "=f"(hi) : "r"(h));
}
__device__ __forceinline__ uint32_t smem_u32(const void* p) {
    uint32_t a;
    asm("{ .reg .u64 t; cvta.to.shared.u64 t, %1; cvt.u32.u64 %0, t; }"
        : "=r"(a) : "l"(p));
    return a;
}

#define SWZ128(x) ((x) ^ (((x) >> 3) & 0x70))

__device__ __forceinline__ void ldsm4(uint32_t r[4], uint32_t a) {
    asm volatile("ldmatrix.sync.aligned.m8n8.x4.shared.b16 {%0,%1,%2,%3}, [%4];"
        : "=r"(r[0]), "=r"(r[1]), "=r"(r[2]), "=r"(r[3]) : "r"(a));
}
__device__ __forceinline__ void ldsm4t(uint32_t r[4], uint32_t a) {
    asm volatile("ldmatrix.sync.aligned.m8n8.x4.trans.shared.b16 {%0,%1,%2,%3}, [%4];"
        : "=r"(r[0]), "=r"(r[1]), "=r"(r[2]), "=r"(r[3]) : "r"(a));
}
__device__ __forceinline__ void mma_hf(float d[4], const uint32_t a[4],
                                       uint32_t b0, uint32_t b1) {
    asm volatile("mma.sync.aligned.m16n8k16.row.col.f32.f16.f16.f32 "
        "{%0,%1,%2,%3}, {%4,%5,%6,%7}, {%8,%9}, {%0,%1,%2,%3};"
        : "+f"(d[0]), "+f"(d[1]), "+f"(d[2]), "+f"(d[3])
        : "r"(a[0]), "r"(a[1]), "r"(a[2]), "r"(a[3]), "r"(b0), "r"(b1));
}
__device__ __forceinline__ void cpa16(uint32_t s, const void* g) {
    asm volatile("cp.async.cg.shared.global [%0], [%1], 16;" :: "r"(s), "l"(g));
}
#define CP_COMMIT() asm volatile("cp.async.commit_group;" ::: "memory")
#define CP_WAIT0()  asm volatile("cp.async.wait_group 0;" ::: "memory")
#define BAR_SYNC(id) asm volatile("bar.sync %0, 128;" :: "r"(id) : "memory")

// ---------------------------------------------------------------------------
// HMMA projection (z = 0:Q, 1:K, 2:V). D[d][n] = sum_c w[d][c] x[c][n] (+bias).
// fp16-split MMA: 3-term for Q/K, 2-term for V. CTA = 128n x 64d, K=512.
// Next k-step's x/w tiles prefetched into registers during the MMA phase.
// Outputs: Q hi-only, K hi+lo, V hi-only.
// ---------------------------------------------------------------------------
__global__ __launch_bounds__(256) void proj_kernel(
    const float* __restrict__ xq, const float* __restrict__ xk, const float* __restrict__ xv,
    const float* __restrict__ wq, const float* __restrict__ bq,
    const float* __restrict__ wk, const float* __restrict__ bk,
    const float* __restrict__ wv, const float* __restrict__ bv)
{
    extern __shared__ char psm[];
    const int sel = blockIdx.z;
    const float* x = (sel == 0) ? xq : (sel == 1) ? xk : xv;
    const float* w = (sel == 0) ? wq : (sel == 1) ? wk : wv;
    const float* bias = (sel == 0) ? bq : (sel == 1) ? bk : bv;

    const int b  = blockIdx.y;
    const int n0 = blockIdx.x * 128;
    const int t  = threadIdx.x, lane = t & 31, wid = t >> 5;
    const int wm = wid >> 2, wn = wid & 3;     // warp grid: 2 (d) x 4 (n)
    const uint32_t sb = smem_u32(psm);

    const float* xb = x + (size_t)b * C_ * HW_ + n0;

    float acc[2][4][4] = {};                   // [mt 16d][nt 8n][frag]

    // Preload k-step 0 into registers.
    float4 xr[8], wr[4];
    #pragma unroll
    for (int i = 0; i < 8; i++) {
        int idx = t + 256 * i;
        int c = idx >> 5, n = (idx & 31) * 4;
        xr[i] = *(const float4*)&xb[(size_t)c * HW_ + n];
    }
    #pragma unroll
    for (int i = 0; i < 4; i++) {
        int idx = t + 256 * i;
        int d = idx >> 4, c = (idx & 15) * 4;
        wr[i] = *(const float4*)&w[(size_t)d * C_ + c];
    }

    for (int kc = 0; kc < C_; kc += 64) {
        __syncthreads();
        // x tile from regs: fp32 -> fp16 h/l, SW128 rows of 64n.
        #pragma unroll
        for (int i = 0; i < 8; i++) {
            int idx = t + 256 * i;
            int c = idx >> 5, n = (idx & 31) * 4;
            float4 xv4 = xr[i];
            uint32_t h0 = packhf(xv4.x, xv4.y), h1 = packhf(xv4.z, xv4.w);
            float f0, f1, f2, f3;
            uph2(h0, f0, f1); uph2(h1, f2, f3);
            uint32_t l0 = packhf(xv4.x - f0, xv4.y - f1);
            uint32_t l1 = packhf(xv4.z - f2, xv4.w - f3);
            int sub = n >> 6, nn = n & 63;
            uint32_t off = (uint32_t)(sub * 8192 + c * 128 + ((nn * 2) ^ ((c & 7) << 4)));
            *(uint2*)(psm + off)         = make_uint2(h0, h1);
            *(uint2*)(psm + 16384 + off) = make_uint2(l0, l1);
        }
        // w tile from regs.
        #pragma unroll
        for (int i = 0; i < 4; i++) {
            int idx = t + 256 * i;
            int d = idx >> 4, c = (idx & 15) * 4;
            float4 wv4 = wr[i];
            uint32_t h0 = packhf(wv4.x, wv4.y), h1 = packhf(wv4.z, wv4.w);
            float f0, f1, f2, f3;
            uph2(h0, f0, f1); uph2(h1, f2, f3);
            uint32_t l0 = packhf(wv4.x - f0, wv4.y - f1);
            uint32_t l1 = packhf(wv4.z - f2, wv4.w - f3);
            uint32_t off = (uint32_t)(d * 128 + ((c * 2) ^ ((d & 7) << 4)));
            *(uint2*)(psm + 32768 + off) = make_uint2(h0, h1);
            *(uint2*)(psm + 40960 + off) = make_uint2(l0, l1);
        }
        // Prefetch next k-step (latency hidden under the MMA phase below).
        if (kc + 64 < C_) {
            #pragma unroll
            for (int i = 0; i < 8; i++) {
                int idx = t + 256 * i;
                int c = idx >> 5, n = (idx & 31) * 4;
                xr[i] = *(const float4*)&xb[(size_t)(kc + 64 + c) * HW_ + n];
            }
            #pragma unroll
            for (int i = 0; i < 4; i++) {
                int idx = t + 256 * i;
                int d = idx >> 4, c = (idx & 15) * 4;
                wr[i] = *(const float4*)&w[(size_t)d * C_ + kc + 64 + c];
            }
        }
        __syncthreads();

        #pragma unroll
        for (int kt = 0; kt < 4; kt++) {
            uint32_t ah[2][4], al[2][4];
            #pragma unroll
            for (int mt = 0; mt < 2; mt++) {
                int row = wm * 32 + mt * 16 + (lane & 15);
                uint32_t off = (uint32_t)(row * 128 +
                    ((kt * 32 + ((lane >> 4) << 4)) ^ ((row & 7) << 4)));
                ldsm4(ah[mt], sb + 32768 + off);
                ldsm4(al[mt], sb + 40960 + off);
            }
            uint32_t bh[8], bl[8];
            #pragma unroll
            for (int hf = 0; hf < 2; hf++) {
                int krow = kt * 16 + (lane & 15);
                int ncol = wn * 32 + hf * 16 + ((lane >> 4) << 3);
                int sub = ncol >> 6, nn = ncol & 63;
                uint32_t off = (uint32_t)(sub * 8192 + krow * 128 +
                    ((nn * 2) ^ ((krow & 7) << 4)));
                ldsm4t(&bh[4 * hf], sb + off);
                ldsm4t(&bl[4 * hf], sb + 16384 + off);
            }
            #pragma unroll
            for (int mt = 0; mt < 2; mt++)
                #pragma unroll
                for (int nt = 0; nt < 4; nt++) {
                    int ib = (nt >> 1) * 4 + (nt & 1) * 2;
                    mma_hf(acc[mt][nt], ah[mt], bh[ib], bh[ib + 1]);
                    mma_hf(acc[mt][nt], ah[mt], bl[ib], bl[ib + 1]);
                    if (sel != 2)
                        mma_hf(acc[mt][nt], al[mt], bh[ib], bh[ib + 1]);
                }
        }
    }

    const int g = lane >> 2, tig = lane & 3;

    if (sel == 2) {
        // V: D[d][n] matches gmem layout -> direct frag stores (hi only).
        #pragma unroll
        for (int mt = 0; mt < 2; mt++) {
            int d0 = wm * 32 + mt * 16 + g, d1 = d0 + 8;
            float b0 = bias[d0], b1 = bias[d1];
            #pragma unroll
            for (int nt = 0; nt < 4; nt++) {
                int n = n0 + wn * 32 + nt * 8 + 2 * tig;
                uint32_t h0 = packhf(acc[mt][nt][0] + b0, acc[mt][nt][1] + b0);
                size_t o0 = ((size_t)b * 64 + d0) * HW_ + n;
                *(uint32_t*)&g_Vh[o0] = h0;
                uint32_t h1 = packhf(acc[mt][nt][2] + b1, acc[mt][nt][3] + b1);
                size_t o1 = ((size_t)b * 64 + d1) * HW_ + n;
                *(uint32_t*)&g_Vh[o1] = h1;
            }
        }
    } else {
        // Q/K: stage D as osm[n][68] fp32, then coalesced [n][64] writes.
        __syncthreads();
        float* osm = (float*)psm;
        const float scale = (sel == 0) ? LOG2E : 1.0f;
        #pragma unroll
        for (int mt = 0; mt < 2; mt++) {
            int d0 = wm * 32 + mt * 16 + g, d1 = d0 + 8;
            float b0 = bias[d0], b1 = bias[d1];
            #pragma unroll
            for (int nt = 0; nt < 4; nt++) {
                int n = wn * 32 + nt * 8 + 2 * tig;
                osm[n * 68 + d0]       = (acc[mt][nt][0] + b0) * scale;
                osm[(n + 1) * 68 + d0] = (acc[mt][nt][1] + b0) * scale;
                osm[n * 68 + d1]       = (acc[mt][nt][2] + b1) * scale;
                osm[(n + 1) * 68 + d1] = (acc[mt][nt][3] + b1) * scale;
            }
        }
        __syncthreads();
        #pragma unroll
        for (int i = 0; i < 8; i++) {
            int idx = t + 256 * i;
            int n = idx >> 4, q = idx & 15;
            float4 vv = *(const float4*)&osm[n * 68 + 4 * q];
            uint32_t h0 = packhf(vv.x, vv.y), h1 = packhf(vv.z, vv.w);
            size_t o = ((size_t)b * HW_ + n0 + n) * 64 + 4 * q;
            if (sel == 0) {
                *(uint2*)&g_Qh[o] = make_uint2(h0, h1);
            } else {
                *(uint2*)&g_Kh[o] = make_uint2(h0, h1);
                float f0, f1, f2, f3;
                uph2(h0, f0, f1); uph2(h1, f2, f3);
                uint32_t l0 = packhf(vv.x - f0, vv.y - f1);
                uint32_t l1 = packhf(vv.z - f2, vv.w - f3);
                *(uint2*)&g_Kl[o] = make_uint2(l0, l1);
            }
        }
    }
}

// ---------------------------------------------------------------------------
// HMMA flash attention (fp16). CTA = (b, 256 queries), two 4-warp groups of
// 128 queries each (own Q region + double-buffered K/V, per-group barriers).
// S: 2-term, Qh*(Kh + Kl) = Qh * K_exact (Q low-split dropped).
// Softmax: online row-max. PV: 1-term.
// ---------------------------------------------------------------------------
#define QG     16384                    // per-group Q (hi only)
#define BUFSZ  24576
#define KVBASE 32768
#define OFF_KH 0
#define OFF_KL 8192
#define OFF_VH 16384
#define SM_TOTAL (KVBASE + 4 * BUFSZ)   // 131072

__global__ __launch_bounds__(256, 1) void attn_kernel(float* __restrict__ out)
{
    extern __shared__ char smem[];
    const uint32_t sb = smem_u32(smem);
    const int t = threadIdx.x, wid = t >> 5, lane = t & 31;
    const int g = t >> 7;                 // query group (warps 0-3 / 4-7)
    const int tg = t & 127;               // thread-in-group
    const int wg = wid & 3;               // warp-in-group
    const int barid = 1 + g;
    const int b = blockIdx.y, n0 = blockIdx.x * BN + g * 128;

    const __half* Gqh = g_Qh + ((size_t)b * HW_ + n0) * 64;
    const __half* Gkh = g_Kh + (size_t)b * HW_ * 64;
    const __half* Gkl = g_Kl + (size_t)b * HW_ * 64;
    const __half* Gvh = g_Vh + (size_t)b * 64 * HW_;

    const uint32_t qbase = sb + g * QG;

    // Stage this group's Q (128 rows x 128B, hi only).
    #pragma unroll
    for (int i = 0; i < 8; i++) {
        int cc = tg + 128 * i;            // 0..1023
        int r = cc >> 3, ch = cc & 7;
        uint32_t dst = qbase + SWZ128((uint32_t)(r * 128 + ch * 16));
        cpa16(dst, Gqh + (size_t)r * 64 + ch * 8);
    }
    CP_COMMIT();

    // Prefetch K/V tile 0 into this group's buffer 0 (KH | KL | VH).
    #pragma unroll
    for (int i = 0; i < 12; i++) {
        int c = tg + 128 * i;             // 0..1535
        int seg = c >> 9;
        int cc = c & 511;
        int r = cc >> 3, ch = cc & 7;
        uint32_t dst = sb + KVBASE + (2 * g) * BUFSZ + seg * 8192
                       + SWZ128((uint32_t)(r * 128 + ch * 16));
        const __half* src =
            (seg == 0) ? Gkh + (size_t)r * 64 + ch * 8 :
            (seg == 1) ? Gkl + (size_t)r * 64 + ch * 8 :
                         Gvh + (size_t)r * HW_ + ch * 8;
        cpa16(dst, src);
    }
    CP_COMMIT();

    float o[2][8][4] = {};
    float mrow[2][2] = {{-1e30f, -1e30f}, {-1e30f, -1e30f}};
    float lsum[2][2] = {};

    for (int m0 = 0, tix = 0; m0 < HW_; m0 += BM, tix++) {
        CP_WAIT0();
        BAR_SYNC(barid);

        if (m0 + BM < HW_) {
            uint32_t nb = sb + KVBASE + (2 * g + ((tix + 1) & 1)) * BUFSZ;
            int mn = m0 + BM;
            #pragma unroll
            for (int i = 0; i < 12; i++) {
                int c = tg + 128 * i;
                int seg = c >> 9;
                int cc = c & 511;
                int r = cc >> 3, ch = cc & 7;
                uint32_t dst = nb + seg * 8192 + SWZ128((uint32_t)(r * 128 + ch * 16));
                const __half* src =
                    (seg == 0) ? Gkh + (size_t)(mn + r) * 64 + ch * 8 :
                    (seg == 1) ? Gkl + (size_t)(mn + r) * 64 + ch * 8 :
                                 Gvh + (size_t)r * HW_ + mn + ch * 8;
                cpa16(dst, src);
            }
            CP_COMMIT();
        }

        const uint32_t bufo = sb + KVBASE + (2 * g + (tix & 1)) * BUFSZ;

        // ---- S = Qh*Kh + Qh*Kl  (32 rows x 64 keys per warp)
        float s[2][8][4] = {};
        #pragma unroll
        for (int kt = 0; kt < 4; kt++) {
            uint32_t kf[16], lf[16];
            #pragma unroll
            for (int jp = 0; jp < 4; jp++) {
                int krow = 16 * jp + ((lane >> 4) << 3) + (lane & 7);
                uint32_t off = SWZ128((uint32_t)(krow * 128 + kt * 32 + ((lane >> 3) & 1) * 16));
                ldsm4(&kf[4 * jp], bufo + OFF_KH + off);
                ldsm4(&lf[4 * jp], bufo + OFF_KL + off);
            }
            uint32_t qh[2][4];
            #pragma unroll
            for (int mt = 0; mt < 2; mt++) {
                int qrow = 32 * wg + 16 * mt + (lane & 15);
                uint32_t qoff = SWZ128((uint32_t)(qrow * 128 + kt * 32 + ((lane >> 4) << 4)));
                ldsm4(qh[mt], qbase + qoff);
            }
            #pragma unroll
            for (int mt = 0; mt < 2; mt++)
                #pragma unroll
                for (int j = 0; j < 8; j++) {
                    int ib = (j >> 1) * 4 + (j & 1) * 2;
                    mma_hf(s[mt][j], qh[mt], kf[ib], kf[ib + 1]);
                    mma_hf(s[mt][j], qh[mt], lf[ib], lf[ib + 1]);
                }
        }

        // ---- Online row max + rescale of O.
        float mn_[2][2], sc[2][2];
        #pragma unroll
        for (int mt = 0; mt < 2; mt++) {
            float tA = -1e30f, tB = -1e30f;
            #pragma unroll
            for (int j = 0; j < 8; j++) {
                tA = fmaxf(tA, fmaxf(s[mt][j][0], s[mt][j][1]));
                tB = fmaxf(tB, fmaxf(s[mt][j][2], s[mt][j][3]));
            }
            tA = fmaxf(tA, __shfl_xor_sync(0xffffffffu, tA, 1));
            tA = fmaxf(tA, __shfl_xor_sync(0xffffffffu, tA, 2));
            tB = fmaxf(tB, __shfl_xor_sync(0xffffffffu, tB, 1));
            tB = fmaxf(tB, __shfl_xor_sync(0xffffffffu, tB, 2));
            mn_[mt][0] = fmaxf(mrow[mt][0], tA);
            mn_[mt][1] = fmaxf(mrow[mt][1], tB);
            sc[mt][0] = ex2f(mrow[mt][0] - mn_[mt][0]);
            sc[mt][1] = ex2f(mrow[mt][1] - mn_[mt][1]);
            mrow[mt][0] = mn_[mt][0];
            mrow[mt][1] = mn_[mt][1];
            #pragma unroll
            for (int j = 0; j < 8; j++) {
                o[mt][j][0] *= sc[mt][0]; o[mt][j][1] *= sc[mt][0];
                o[mt][j][2] *= sc[mt][1]; o[mt][j][3] *= sc[mt][1];
            }
        }

        // ---- Per 16-key chunk: exponentiate P, then PV MMAs (1-term).
        float ts[2][2] = {};
        #pragma unroll
        for (int kt = 0; kt < 4; kt++) {
            uint32_t vf[16];
            #pragma unroll
            for (int jp = 0; jp < 4; jp++) {
                int vrow = 16 * jp + ((lane >> 4) << 3) + (lane & 7);
                uint32_t off = SWZ128((uint32_t)(vrow * 128 + kt * 32 + ((lane >> 3) & 1) * 16));
                ldsm4(&vf[4 * jp], bufo + OFF_VH + off);
            }
            uint32_t ap[2][4];
            #pragma unroll
            for (int mt = 0; mt < 2; mt++) {
                int j0 = 2 * kt, j1 = 2 * kt + 1;
                float p0 = ex2f(s[mt][j0][0] - mn_[mt][0]), p1 = ex2f(s[mt][j0][1] - mn_[mt][0]);
                float p2 = ex2f(s[mt][j0][2] - mn_[mt][1]), p3 = ex2f(s[mt][j0][3] - mn_[mt][1]);
                float p4 = ex2f(s[mt][j1][0] - mn_[mt][0]), p5 = ex2f(s[mt][j1][1] - mn_[mt][0]);
                float p6 = ex2f(s[mt][j1][2] - mn_[mt][1]), p7 = ex2f(s[mt][j1][3] - mn_[mt][1]);
                ts[mt][0] += (p0 + p1) + (p4 + p5);
                ts[mt][1] += (p2 + p3) + (p6 + p7);
                ap[mt][0] = packhf(p0, p1); ap[mt][1] = packhf(p2, p3);
                ap[mt][2] = packhf(p4, p5); ap[mt][3] = packhf(p6, p7);
            }
            #pragma unroll
            for (int mt = 0; mt < 2; mt++)
                #pragma unroll
                for (int j = 0; j < 8; j++) {
                    int ib = (j >> 1) * 4 + (j & 1) * 2;
                    mma_hf(o[mt][j], ap[mt], vf[ib], vf[ib + 1]);
                }
        }
        #pragma unroll
        for (int mt = 0; mt < 2; mt++) {
            lsum[mt][0] = lsum[mt][0] * sc[mt][0] + ts[mt][0];
            lsum[mt][1] = lsum[mt][1] * sc[mt][1] + ts[mt][1];
        }
    }

    // ---- Row-sum reduction across the quad, normalize.
    float inv[2][2];
    #pragma unroll
    for (int mt = 0; mt < 2; mt++)
        #pragma unroll
        for (int h = 0; h < 2; h++) {
            float l = lsum[mt][h];
            l += __shfl_xor_sync(0xffffffffu, l, 1);
            l += __shfl_xor_sync(0xffffffffu, l, 2);
            inv[mt][h] = 1.0f / l;
        }

    // ---- Stage O[dd][n] in smem (stride 260), then coalesced 8-head stores.
    __syncthreads();   // full-CTA: both groups done with their loops
    float* osm = (float*)smem;
    {
        int ddb = 2 * (lane & 3);
        #pragma unroll
        for (int mt = 0; mt < 2; mt++) {
            int row = g * 128 + 32 * wg + 16 * mt + (lane >> 2);
            #pragma unroll
            for (int j = 0; j < 8; j++) {
                int dd = 8 * j + ddb;
                osm[dd * 260 + row]           = o[mt][j][0] * inv[mt][0];
                osm[(dd + 1) * 260 + row]     = o[mt][j][1] * inv[mt][0];
                osm[dd * 260 + row + 8]       = o[mt][j][2] * inv[mt][1];
                osm[(dd + 1) * 260 + row + 8] = o[mt][j][3] * inv[mt][1];
            }
        }
    }
    __syncthreads();

    float* ob = out + (size_t)b * C_ * HW_ + blockIdx.x * BN;
    #pragma unroll
    for (int i = 0; i < 16; i++) {
        int c = t + 256 * i;              // 0..4095
        int dd = c >> 6, nc = c & 63;
        float4 v = *(const float4*)&osm[dd * 260 + 4 * nc];
        #pragma unroll
        for (int h = 0; h < 8; h++)
            *(float4*)&ob[(size_t)(h * 64 + dd) * HW_ + 4 * nc] = v;
    }
}

// ---------------------------------------------------------------------------
extern "C" void kernel_launch(void* const* d_in, const int* in_sizes, int n_in,
                              void* d_out, int out_size)
{
    (void)in_sizes; (void)n_in; (void)out_size;
    const float* q  = (const float*)d_in[0];
    const float* k  = (const float*)d_in[1];
    const float* v  = (const float*)d_in[2];
    const float* wq = (const float*)d_in[3];
    const float* bq = (const float*)d_in[4];
    const float* wk = (const float*)d_in[5];
    const float* bk = (const float*)d_in[6];
    const float* wv = (const float*)d_in[7];
    const float* bv = (const float*)d_in[8];
    float* out = (float*)d_out;

    const int PROJ_SMEM = 49152;
    cudaFuncSetAttribute(proj_kernel,
                         cudaFuncAttributeMaxDynamicSharedMemorySize, PROJ_SMEM);
    cudaFuncSetAttribute(attn_kernel,
                         cudaFuncAttributeMaxDynamicSharedMemorySize, SM_TOTAL);

    dim3 pgrid(HW_ / 128, B_, 3);
    proj_kernel<<<pgrid, 256, PROJ_SMEM>>>(q, k, v, wq, bq, wk, bk, wv, bv);

    dim3 agrid(HW_ / BN, B_);
    attn_kernel<<<agrid, 256, SM_TOTAL>>>(out);
}